// round 2
// baseline (speedup 1.0000x reference)
#include <cuda_runtime.h>
#include <math.h>

// Problem constants
#define TK    4096          // B*T tokens
#define CDIM  1024
#define NEXP  8
#define TOPK  2
#define HDIM  2736
#define NPAIR (TK*TOPK)     // 8192

// ---------------- scratch (static device globals; no allocation) -------------
__device__ int   g_cnt[NEXP];
__device__ int   g_off[NEXP];
__device__ int   g_cur[NEXP];
__device__ float g_psum[NEXP];
__device__ int   g_soff[1];
__device__ int   g_scnt[1];
__device__ int   g_top_i[TK*TOPK];
__device__ float g_top_w[TK*TOPK];
__device__ int   g_perm[NPAIR];
__device__ float g_pw[NPAIR];
__device__ int   g_pos[TK*TOPK];
__device__ float g_xg[(size_t)NPAIR*CDIM];   // gathered activations  (33.5MB)
__device__ float g_h [(size_t)NPAIR*HDIM];   // expert swiglu hidden  (89.7MB)
__device__ float g_yd[(size_t)NPAIR*CDIM];   // expert down output    (33.5MB)
__device__ float g_hs[(size_t)TK*HDIM];      // shared hidden         (44.8MB)
__device__ float g_ys[(size_t)TK*CDIM];      // shared down output    (16.8MB)

// ---------------- small kernels ----------------------------------------------
__global__ void zero_kernel() {
    int t = threadIdx.x;
    if (t < NEXP) { g_cnt[t] = 0; g_psum[t] = 0.f; }
}

// One warp per token: logits (1024 dot 8), top-2 softmax weights, full softmax
// accumulation for aux loss, expert counts.
__global__ void router_kernel(const float* __restrict__ x,
                              const float* __restrict__ rw) {
    int warp = threadIdx.x >> 5;
    int lane = threadIdx.x & 31;
    int t = blockIdx.x * (blockDim.x >> 5) + warp;
    if (t >= TK) return;
    const float* xr = x + (size_t)t * CDIM;
    float acc[NEXP];
#pragma unroll
    for (int e = 0; e < NEXP; e++) acc[e] = 0.f;
    for (int c = lane; c < CDIM; c += 32) {
        float xv = xr[c];
        const float4* rp = (const float4*)(rw + (size_t)c * NEXP);
        float4 r0 = rp[0], r1 = rp[1];
        acc[0] += xv * r0.x; acc[1] += xv * r0.y;
        acc[2] += xv * r0.z; acc[3] += xv * r0.w;
        acc[4] += xv * r1.x; acc[5] += xv * r1.y;
        acc[6] += xv * r1.z; acc[7] += xv * r1.w;
    }
#pragma unroll
    for (int e = 0; e < NEXP; e++) {
#pragma unroll
        for (int s = 16; s; s >>= 1)
            acc[e] += __shfl_xor_sync(0xffffffffu, acc[e], s);
    }
    if (lane == 0) {
        // top-2 (first-index wins ties, matching top_k ordering)
        int i0 = 0; float v0 = acc[0];
#pragma unroll
        for (int e = 1; e < NEXP; e++) if (acc[e] > v0) { v0 = acc[e]; i0 = e; }
        int i1 = -1; float v1 = -INFINITY;
#pragma unroll
        for (int e = 0; e < NEXP; e++)
            if (e != i0 && acc[e] > v1) { v1 = acc[e]; i1 = e; }
        float w0 = 1.f / (1.f + expf(v1 - v0));
        float w1 = 1.f - w0;
        g_top_i[t*2+0] = i0; g_top_i[t*2+1] = i1;
        g_top_w[t*2+0] = w0; g_top_w[t*2+1] = w1;
        atomicAdd(&g_cnt[i0], 1);
        atomicAdd(&g_cnt[i1], 1);
        // full softmax for aux p
        float s = 0.f, pe[NEXP];
#pragma unroll
        for (int e = 0; e < NEXP; e++) { pe[e] = expf(acc[e] - v0); s += pe[e]; }
        float inv = 1.f / s;
#pragma unroll
        for (int e = 0; e < NEXP; e++) atomicAdd(&g_psum[e], pe[e] * inv);
    }
}

__global__ void offsets_kernel() {
    int o = 0;
    for (int e = 0; e < NEXP; e++) { g_off[e] = o; g_cur[e] = o; o += g_cnt[e]; }
    g_soff[0] = 0; g_scnt[0] = TK;
}

__global__ void scatter_kernel() {
    int t = blockIdx.x * blockDim.x + threadIdx.x;
    if (t >= TK) return;
#pragma unroll
    for (int k = 0; k < TOPK; k++) {
        int e = g_top_i[t*2+k];
        int pos = atomicAdd(&g_cur[e], 1);
        g_perm[pos] = t;
        g_pw[pos]   = g_top_w[t*2+k];
        g_pos[t*2+k] = pos;
    }
}

__global__ void gather_kernel(const float* __restrict__ x) {
    int p = blockIdx.x;
    int src = g_perm[p];
    const float4* s = (const float4*)(x + (size_t)src * CDIM);
    float4*       d = (float4*)(g_xg + (size_t)p * CDIM);
    d[threadIdx.x] = s[threadIdx.x];   // 256 threads × float4 == 1024 floats
}

// ---------------- GEMMs ------------------------------------------------------
#define BM 64
#define BN 64
#define BK 16

// Fused gate/up GEMM + SwiGLU. A: rows (absolute index) x Kdim, stride ldA.
// Wg/Wu: per-expert Kdim x HDIM (stride HDIM), expert stride wstride.
__global__ void __launch_bounds__(256)
gateup_gemm(const float* __restrict__ A, int ldA,
            const float* __restrict__ Wg, const float* __restrict__ Wu,
            size_t wstride, float* __restrict__ Hout,
            const int* __restrict__ offs, const int* __restrict__ cnts,
            int Kdim)
{
    int e = blockIdx.z;
    int off = offs[e], cnt = cnts[e];
    int row0 = off + blockIdx.y * BM;
    int rowEnd = off + cnt;
    if (row0 >= rowEnd) return;
    int n0 = blockIdx.x * BN;
    const float* wgp = Wg + (size_t)e * wstride;
    const float* wup = Wu + (size_t)e * wstride;

    __shared__ float As[BK][BM];
    __shared__ float Bg[BK][BN];
    __shared__ float Bu[BK][BN];

    int tid = threadIdx.x;
    int tx = tid & 15, ty = tid >> 4;

    float ag[4][4], au[4][4];
#pragma unroll
    for (int i = 0; i < 4; i++)
#pragma unroll
        for (int j = 0; j < 4; j++) { ag[i][j] = 0.f; au[i][j] = 0.f; }

    int arow = tid >> 2;
    int ac4  = (tid & 3) * 4;
    int brow = tid >> 4;
    int bc4  = (tid & 15) * 4;
    int aRowIdx = min(row0 + arow, rowEnd - 1);
    const float* aptr = A + (size_t)aRowIdx * ldA + ac4;
    int bcol = n0 + bc4;
    bool bvalid = bcol < HDIM;
    const float* bgp = wgp + (size_t)brow * HDIM + bcol;
    const float* bup = wup + (size_t)brow * HDIM + bcol;

    for (int kc = 0; kc < Kdim; kc += BK) {
        float4 av = *(const float4*)(aptr + kc);
        float4 gv = bvalid ? *(const float4*)(bgp + (size_t)kc * HDIM)
                           : make_float4(0.f,0.f,0.f,0.f);
        float4 uv = bvalid ? *(const float4*)(bup + (size_t)kc * HDIM)
                           : make_float4(0.f,0.f,0.f,0.f);
        __syncthreads();
        As[ac4+0][arow] = av.x; As[ac4+1][arow] = av.y;
        As[ac4+2][arow] = av.z; As[ac4+3][arow] = av.w;
        *(float4*)&Bg[brow][bc4] = gv;
        *(float4*)&Bu[brow][bc4] = uv;
        __syncthreads();
#pragma unroll
        for (int k = 0; k < BK; k++) {
            float4 a4 = *(const float4*)&As[k][ty*4];
            float4 g4 = *(const float4*)&Bg[k][tx*4];
            float4 u4 = *(const float4*)&Bu[k][tx*4];
            float a_[4] = {a4.x, a4.y, a4.z, a4.w};
            float g_[4] = {g4.x, g4.y, g4.z, g4.w};
            float u_[4] = {u4.x, u4.y, u4.z, u4.w};
#pragma unroll
            for (int i = 0; i < 4; i++)
#pragma unroll
                for (int j = 0; j < 4; j++) {
                    ag[i][j] += a_[i] * g_[j];
                    au[i][j] += a_[i] * u_[j];
                }
        }
    }
#pragma unroll
    for (int i = 0; i < 4; i++) {
        int r = row0 + ty*4 + i;
        if (r < rowEnd) {
#pragma unroll
            for (int j = 0; j < 4; j++) {
                int ccol = n0 + tx*4 + j;
                if (ccol < HDIM) {
                    float g = ag[i][j], u = au[i][j];
                    Hout[(size_t)r * HDIM + ccol] = (g / (1.f + expf(-g))) * u;
                }
            }
        }
    }
}

// Down-projection GEMM with optional per-row scale.
__global__ void __launch_bounds__(256)
down_gemm(const float* __restrict__ A, int ldA,
          const float* __restrict__ W, size_t wstride,
          float* __restrict__ Y, const float* __restrict__ scale,
          const int* __restrict__ offs, const int* __restrict__ cnts,
          int Kdim, int Ndim)
{
    int e = blockIdx.z;
    int off = offs[e], cnt = cnts[e];
    int row0 = off + blockIdx.y * BM;
    int rowEnd = off + cnt;
    if (row0 >= rowEnd) return;
    int n0 = blockIdx.x * BN;
    const float* wp = W + (size_t)e * wstride;

    __shared__ float As[BK][BM];
    __shared__ float Bs[BK][BN];

    int tid = threadIdx.x;
    int tx = tid & 15, ty = tid >> 4;

    float acc[4][4];
#pragma unroll
    for (int i = 0; i < 4; i++)
#pragma unroll
        for (int j = 0; j < 4; j++) acc[i][j] = 0.f;

    int arow = tid >> 2;
    int ac4  = (tid & 3) * 4;
    int brow = tid >> 4;
    int bc4  = (tid & 15) * 4;
    int aRowIdx = min(row0 + arow, rowEnd - 1);
    const float* aptr = A + (size_t)aRowIdx * ldA + ac4;
    int bcol = n0 + bc4;
    bool bvalid = bcol < Ndim;
    const float* bp = wp + (size_t)brow * Ndim + bcol;

    for (int kc = 0; kc < Kdim; kc += BK) {
        float4 av = *(const float4*)(aptr + kc);
        float4 bv = bvalid ? *(const float4*)(bp + (size_t)kc * Ndim)
                           : make_float4(0.f,0.f,0.f,0.f);
        __syncthreads();
        As[ac4+0][arow] = av.x; As[ac4+1][arow] = av.y;
        As[ac4+2][arow] = av.z; As[ac4+3][arow] = av.w;
        *(float4*)&Bs[brow][bc4] = bv;
        __syncthreads();
#pragma unroll
        for (int k = 0; k < BK; k++) {
            float4 a4 = *(const float4*)&As[k][ty*4];
            float4 b4 = *(const float4*)&Bs[k][tx*4];
            float a_[4] = {a4.x, a4.y, a4.z, a4.w};
            float b_[4] = {b4.x, b4.y, b4.z, b4.w};
#pragma unroll
            for (int i = 0; i < 4; i++)
#pragma unroll
                for (int j = 0; j < 4; j++) acc[i][j] += a_[i] * b_[j];
        }
    }
#pragma unroll
    for (int i = 0; i < 4; i++) {
        int r = row0 + ty*4 + i;
        if (r < rowEnd) {
            float s = scale ? scale[r] : 1.f;
#pragma unroll
            for (int j = 0; j < 4; j++) {
                int ccol = n0 + tx*4 + j;
                if (ccol < Ndim)
                    Y[(size_t)r * Ndim + ccol] = acc[i][j] * s;
            }
        }
    }
}

// out[t] = yd[pos0] + yd[pos1] + ys[t]  (fully deterministic combine)
__global__ void combine_kernel(float* __restrict__ out) {
    int t = blockIdx.x;
    int p0 = g_pos[t*2+0], p1 = g_pos[t*2+1];
    const float4* a = (const float4*)(g_yd + (size_t)p0 * CDIM);
    const float4* b = (const float4*)(g_yd + (size_t)p1 * CDIM);
    const float4* c = (const float4*)(g_ys + (size_t)t  * CDIM);
    float4* o = (float4*)(out + (size_t)t * CDIM);
    int i = threadIdx.x;
    float4 va = a[i], vb = b[i], vc = c[i];
    o[i] = make_float4(va.x+vb.x+vc.x, va.y+vb.y+vc.y,
                       va.z+vb.z+vc.z, va.w+vb.w+vc.w);
}

__global__ void aux_kernel(float* __restrict__ dst) {
    float a = 0.f;
    for (int e = 0; e < NEXP; e++) {
        float f = (float)g_cnt[e] / (float)(TK * TOPK);
        float p = g_psum[e] / (float)TK;
        a += f * p;
    }
    dst[0] = (float)NEXP * a;
}

// ---------------- launch -----------------------------------------------------
extern "C" void kernel_launch(void* const* d_in, const int* in_sizes, int n_in,
                              void* d_out, int out_size) {
    const float* x  = (const float*)d_in[0];
    const float* rw = (const float*)d_in[1];
    const float* wg = (const float*)d_in[2];
    const float* wu = (const float*)d_in[3];
    const float* wd = (const float*)d_in[4];
    const float* sg = (const float*)d_in[5];
    const float* su = (const float*)d_in[6];
    const float* sd = (const float*)d_in[7];
    float* out = (float*)d_out;

    float *p_xg, *p_h, *p_yd, *p_hs, *p_ys, *p_pw;
    int *p_off, *p_cnt, *p_soff, *p_scnt;
    cudaGetSymbolAddress((void**)&p_xg,  g_xg);
    cudaGetSymbolAddress((void**)&p_h,   g_h);
    cudaGetSymbolAddress((void**)&p_yd,  g_yd);
    cudaGetSymbolAddress((void**)&p_hs,  g_hs);
    cudaGetSymbolAddress((void**)&p_ys,  g_ys);
    cudaGetSymbolAddress((void**)&p_pw,  g_pw);
    cudaGetSymbolAddress((void**)&p_off, g_off);
    cudaGetSymbolAddress((void**)&p_cnt, g_cnt);
    cudaGetSymbolAddress((void**)&p_soff, g_soff);
    cudaGetSymbolAddress((void**)&p_scnt, g_scnt);

    zero_kernel<<<1, 32>>>();
    router_kernel<<<TK/4, 128>>>(x, rw);
    offsets_kernel<<<1, 1>>>();
    scatter_kernel<<<16, 256>>>();
    gather_kernel<<<NPAIR, 256>>>(x);

    // expert gate/up + SwiGLU:  h = silu(xg @ wg_e) * (xg @ wu_e)
    gateup_gemm<<<dim3((HDIM+BN-1)/BN, NPAIR/BM, NEXP), 256>>>(
        p_xg, CDIM, wg, wu, (size_t)CDIM*HDIM, p_h, p_off, p_cnt, CDIM);
    // shared gate/up
    gateup_gemm<<<dim3((HDIM+BN-1)/BN, TK/BM, 1), 256>>>(
        x, CDIM, sg, su, 0, p_hs, p_soff, p_scnt, CDIM);

    // expert down:  yd = (h @ wd_e) * router_weight
    down_gemm<<<dim3(CDIM/BN, NPAIR/BM, NEXP), 256>>>(
        p_h, HDIM, wd, (size_t)HDIM*CDIM, p_yd, p_pw, p_off, p_cnt, HDIM, CDIM);
    // shared down
    down_gemm<<<dim3(CDIM/BN, TK/BM, 1), 256>>>(
        p_hs, HDIM, sd, 0, p_ys, nullptr, p_soff, p_scnt, HDIM, CDIM);

    combine_kernel<<<TK, 256>>>(out);

    if (out_size > TK * CDIM)
        aux_kernel<<<1, 1>>>(out + (size_t)TK * CDIM);
}

// round 3
// speedup vs baseline: 1.0001x; 1.0001x over previous
#include <cuda_runtime.h>
#include <math.h>

// Problem constants
#define TK    4096          // B*T tokens
#define CDIM  1024
#define NEXP  8
#define TOPK  2
#define HDIM  2736
#define NPAIR (TK*TOPK)     // 8192

// ---------------- scratch (static device globals; no allocation) -------------
__device__ int   g_cnt[NEXP];
__device__ int   g_off[NEXP];
__device__ int   g_cur[NEXP];
__device__ float g_psum[NEXP];
__device__ int   g_soff[1];
__device__ int   g_scnt[1];
__device__ int   g_top_i[TK*TOPK];
__device__ float g_top_w[TK*TOPK];
__device__ int   g_perm[NPAIR];
__device__ float g_pw[NPAIR];
__device__ int   g_pos[TK*TOPK];
__device__ float g_xg[(size_t)NPAIR*CDIM];   // gathered activations  (33.5MB)
__device__ float g_h [(size_t)NPAIR*HDIM];   // expert swiglu hidden  (89.7MB)
__device__ float g_yd[(size_t)NPAIR*CDIM];   // expert down output    (33.5MB)
__device__ float g_hs[(size_t)TK*HDIM];      // shared hidden         (44.8MB)
__device__ float g_ys[(size_t)TK*CDIM];      // shared down output    (16.8MB)

// ---------------- small kernels ----------------------------------------------
__global__ void zero_kernel() {
    int t = threadIdx.x;
    if (t < NEXP) { g_cnt[t] = 0; g_psum[t] = 0.f; }
}

// One warp per token: logits (1024 dot 8), top-2 softmax weights, full softmax
// accumulation for aux loss, expert counts.
__global__ void router_kernel(const float* __restrict__ x,
                              const float* __restrict__ rw) {
    int warp = threadIdx.x >> 5;
    int lane = threadIdx.x & 31;
    int t = blockIdx.x * (blockDim.x >> 5) + warp;
    if (t >= TK) return;
    const float* xr = x + (size_t)t * CDIM;
    float acc[NEXP];
#pragma unroll
    for (int e = 0; e < NEXP; e++) acc[e] = 0.f;
    for (int c = lane; c < CDIM; c += 32) {
        float xv = xr[c];
        const float4* rp = (const float4*)(rw + (size_t)c * NEXP);
        float4 r0 = rp[0], r1 = rp[1];
        acc[0] += xv * r0.x; acc[1] += xv * r0.y;
        acc[2] += xv * r0.z; acc[3] += xv * r0.w;
        acc[4] += xv * r1.x; acc[5] += xv * r1.y;
        acc[6] += xv * r1.z; acc[7] += xv * r1.w;
    }
#pragma unroll
    for (int e = 0; e < NEXP; e++) {
#pragma unroll
        for (int s = 16; s; s >>= 1)
            acc[e] += __shfl_xor_sync(0xffffffffu, acc[e], s);
    }
    if (lane == 0) {
        // top-2 (first-index wins ties, matching top_k ordering)
        int i0 = 0; float v0 = acc[0];
#pragma unroll
        for (int e = 1; e < NEXP; e++) if (acc[e] > v0) { v0 = acc[e]; i0 = e; }
        int i1 = -1; float v1 = -INFINITY;
#pragma unroll
        for (int e = 0; e < NEXP; e++)
            if (e != i0 && acc[e] > v1) { v1 = acc[e]; i1 = e; }
        float w0 = 1.f / (1.f + expf(v1 - v0));
        float w1 = 1.f - w0;
        g_top_i[t*2+0] = i0; g_top_i[t*2+1] = i1;
        g_top_w[t*2+0] = w0; g_top_w[t*2+1] = w1;
        atomicAdd(&g_cnt[i0], 1);
        atomicAdd(&g_cnt[i1], 1);
        // full softmax for aux p
        float s = 0.f, pe[NEXP];
#pragma unroll
        for (int e = 0; e < NEXP; e++) { pe[e] = expf(acc[e] - v0); s += pe[e]; }
        float inv = 1.f / s;
#pragma unroll
        for (int e = 0; e < NEXP; e++) atomicAdd(&g_psum[e], pe[e] * inv);
    }
}

__global__ void offsets_kernel() {
    int o = 0;
    for (int e = 0; e < NEXP; e++) { g_off[e] = o; g_cur[e] = o; o += g_cnt[e]; }
    g_soff[0] = 0; g_scnt[0] = TK;
}

__global__ void scatter_kernel() {
    int t = blockIdx.x * blockDim.x + threadIdx.x;
    if (t >= TK) return;
#pragma unroll
    for (int k = 0; k < TOPK; k++) {
        int e = g_top_i[t*2+k];
        int pos = atomicAdd(&g_cur[e], 1);
        g_perm[pos] = t;
        g_pw[pos]   = g_top_w[t*2+k];
        g_pos[t*2+k] = pos;
    }
}

__global__ void gather_kernel(const float* __restrict__ x) {
    int p = blockIdx.x;
    int src = g_perm[p];
    const float4* s = (const float4*)(x + (size_t)src * CDIM);
    float4*       d = (float4*)(g_xg + (size_t)p * CDIM);
    d[threadIdx.x] = s[threadIdx.x];   // 256 threads × float4 == 1024 floats
}

// ---------------- GEMMs ------------------------------------------------------
#define BM 64
#define BN 64
#define BK 16

// Fused gate/up GEMM + SwiGLU. A: rows (absolute index) x Kdim, stride ldA.
// Wg/Wu: per-expert Kdim x HDIM (stride HDIM), expert stride wstride.
__global__ void __launch_bounds__(256)
gateup_gemm(const float* __restrict__ A, int ldA,
            const float* __restrict__ Wg, const float* __restrict__ Wu,
            size_t wstride, float* __restrict__ Hout,
            const int* __restrict__ offs, const int* __restrict__ cnts,
            int Kdim)
{
    int e = blockIdx.z;
    int off = offs[e], cnt = cnts[e];
    int row0 = off + blockIdx.y * BM;
    int rowEnd = off + cnt;
    if (row0 >= rowEnd) return;
    int n0 = blockIdx.x * BN;
    const float* wgp = Wg + (size_t)e * wstride;
    const float* wup = Wu + (size_t)e * wstride;

    __shared__ float As[BK][BM];
    __shared__ float Bg[BK][BN];
    __shared__ float Bu[BK][BN];

    int tid = threadIdx.x;
    int tx = tid & 15, ty = tid >> 4;

    float ag[4][4], au[4][4];
#pragma unroll
    for (int i = 0; i < 4; i++)
#pragma unroll
        for (int j = 0; j < 4; j++) { ag[i][j] = 0.f; au[i][j] = 0.f; }

    int arow = tid >> 2;
    int ac4  = (tid & 3) * 4;
    int brow = tid >> 4;
    int bc4  = (tid & 15) * 4;
    int aRowIdx = min(row0 + arow, rowEnd - 1);
    const float* aptr = A + (size_t)aRowIdx * ldA + ac4;
    int bcol = n0 + bc4;
    bool bvalid = bcol < HDIM;
    const float* bgp = wgp + (size_t)brow * HDIM + bcol;
    const float* bup = wup + (size_t)brow * HDIM + bcol;

    for (int kc = 0; kc < Kdim; kc += BK) {
        float4 av = *(const float4*)(aptr + kc);
        float4 gv = bvalid ? *(const float4*)(bgp + (size_t)kc * HDIM)
                           : make_float4(0.f,0.f,0.f,0.f);
        float4 uv = bvalid ? *(const float4*)(bup + (size_t)kc * HDIM)
                           : make_float4(0.f,0.f,0.f,0.f);
        __syncthreads();
        As[ac4+0][arow] = av.x; As[ac4+1][arow] = av.y;
        As[ac4+2][arow] = av.z; As[ac4+3][arow] = av.w;
        *(float4*)&Bg[brow][bc4] = gv;
        *(float4*)&Bu[brow][bc4] = uv;
        __syncthreads();
#pragma unroll
        for (int k = 0; k < BK; k++) {
            float4 a4 = *(const float4*)&As[k][ty*4];
            float4 g4 = *(const float4*)&Bg[k][tx*4];
            float4 u4 = *(const float4*)&Bu[k][tx*4];
            float a_[4] = {a4.x, a4.y, a4.z, a4.w};
            float g_[4] = {g4.x, g4.y, g4.z, g4.w};
            float u_[4] = {u4.x, u4.y, u4.z, u4.w};
#pragma unroll
            for (int i = 0; i < 4; i++)
#pragma unroll
                for (int j = 0; j < 4; j++) {
                    ag[i][j] += a_[i] * g_[j];
                    au[i][j] += a_[i] * u_[j];
                }
        }
    }
#pragma unroll
    for (int i = 0; i < 4; i++) {
        int r = row0 + ty*4 + i;
        if (r < rowEnd) {
#pragma unroll
            for (int j = 0; j < 4; j++) {
                int ccol = n0 + tx*4 + j;
                if (ccol < HDIM) {
                    float g = ag[i][j], u = au[i][j];
                    Hout[(size_t)r * HDIM + ccol] = (g / (1.f + expf(-g))) * u;
                }
            }
        }
    }
}

// Down-projection GEMM with optional per-row scale.
__global__ void __launch_bounds__(256)
down_gemm(const float* __restrict__ A, int ldA,
          const float* __restrict__ W, size_t wstride,
          float* __restrict__ Y, const float* __restrict__ scale,
          const int* __restrict__ offs, const int* __restrict__ cnts,
          int Kdim, int Ndim)
{
    int e = blockIdx.z;
    int off = offs[e], cnt = cnts[e];
    int row0 = off + blockIdx.y * BM;
    int rowEnd = off + cnt;
    if (row0 >= rowEnd) return;
    int n0 = blockIdx.x * BN;
    const float* wp = W + (size_t)e * wstride;

    __shared__ float As[BK][BM];
    __shared__ float Bs[BK][BN];

    int tid = threadIdx.x;
    int tx = tid & 15, ty = tid >> 4;

    float acc[4][4];
#pragma unroll
    for (int i = 0; i < 4; i++)
#pragma unroll
        for (int j = 0; j < 4; j++) acc[i][j] = 0.f;

    int arow = tid >> 2;
    int ac4  = (tid & 3) * 4;
    int brow = tid >> 4;
    int bc4  = (tid & 15) * 4;
    int aRowIdx = min(row0 + arow, rowEnd - 1);
    const float* aptr = A + (size_t)aRowIdx * ldA + ac4;
    int bcol = n0 + bc4;
    bool bvalid = bcol < Ndim;
    const float* bp = wp + (size_t)brow * Ndim + bcol;

    for (int kc = 0; kc < Kdim; kc += BK) {
        float4 av = *(const float4*)(aptr + kc);
        float4 bv = bvalid ? *(const float4*)(bp + (size_t)kc * Ndim)
                           : make_float4(0.f,0.f,0.f,0.f);
        __syncthreads();
        As[ac4+0][arow] = av.x; As[ac4+1][arow] = av.y;
        As[ac4+2][arow] = av.z; As[ac4+3][arow] = av.w;
        *(float4*)&Bs[brow][bc4] = bv;
        __syncthreads();
#pragma unroll
        for (int k = 0; k < BK; k++) {
            float4 a4 = *(const float4*)&As[k][ty*4];
            float4 b4 = *(const float4*)&Bs[k][tx*4];
            float a_[4] = {a4.x, a4.y, a4.z, a4.w};
            float b_[4] = {b4.x, b4.y, b4.z, b4.w};
#pragma unroll
            for (int i = 0; i < 4; i++)
#pragma unroll
                for (int j = 0; j < 4; j++) acc[i][j] += a_[i] * b_[j];
        }
    }
#pragma unroll
    for (int i = 0; i < 4; i++) {
        int r = row0 + ty*4 + i;
        if (r < rowEnd) {
            float s = scale ? scale[r] : 1.f;
#pragma unroll
            for (int j = 0; j < 4; j++) {
                int ccol = n0 + tx*4 + j;
                if (ccol < Ndim)
                    Y[(size_t)r * Ndim + ccol] = acc[i][j] * s;
            }
        }
    }
}

// out[t] = yd[pos0] + yd[pos1] + ys[t]  (fully deterministic combine)
__global__ void combine_kernel(float* __restrict__ out) {
    int t = blockIdx.x;
    int p0 = g_pos[t*2+0], p1 = g_pos[t*2+1];
    const float4* a = (const float4*)(g_yd + (size_t)p0 * CDIM);
    const float4* b = (const float4*)(g_yd + (size_t)p1 * CDIM);
    const float4* c = (const float4*)(g_ys + (size_t)t  * CDIM);
    float4* o = (float4*)(out + (size_t)t * CDIM);
    int i = threadIdx.x;
    float4 va = a[i], vb = b[i], vc = c[i];
    o[i] = make_float4(va.x+vb.x+vc.x, va.y+vb.y+vc.y,
                       va.z+vb.z+vc.z, va.w+vb.w+vc.w);
}

__global__ void aux_kernel(float* __restrict__ dst) {
    float a = 0.f;
    for (int e = 0; e < NEXP; e++) {
        float f = (float)g_cnt[e] / (float)(TK * TOPK);
        float p = g_psum[e] / (float)TK;
        a += f * p;
    }
    dst[0] = (float)NEXP * a;
}

// ---------------- launch -----------------------------------------------------
extern "C" void kernel_launch(void* const* d_in, const int* in_sizes, int n_in,
                              void* d_out, int out_size) {
    const float* x  = (const float*)d_in[0];
    const float* rw = (const float*)d_in[1];
    const float* wg = (const float*)d_in[2];
    const float* wu = (const float*)d_in[3];
    const float* wd = (const float*)d_in[4];
    const float* sg = (const float*)d_in[5];
    const float* su = (const float*)d_in[6];
    const float* sd = (const float*)d_in[7];
    float* out = (float*)d_out;

    float *p_xg, *p_h, *p_yd, *p_hs, *p_ys, *p_pw;
    int *p_off, *p_cnt, *p_soff, *p_scnt;
    cudaGetSymbolAddress((void**)&p_xg,  g_xg);
    cudaGetSymbolAddress((void**)&p_h,   g_h);
    cudaGetSymbolAddress((void**)&p_yd,  g_yd);
    cudaGetSymbolAddress((void**)&p_hs,  g_hs);
    cudaGetSymbolAddress((void**)&p_ys,  g_ys);
    cudaGetSymbolAddress((void**)&p_pw,  g_pw);
    cudaGetSymbolAddress((void**)&p_off, g_off);
    cudaGetSymbolAddress((void**)&p_cnt, g_cnt);
    cudaGetSymbolAddress((void**)&p_soff, g_soff);
    cudaGetSymbolAddress((void**)&p_scnt, g_scnt);

    zero_kernel<<<1, 32>>>();
    router_kernel<<<TK/4, 128>>>(x, rw);
    offsets_kernel<<<1, 1>>>();
    scatter_kernel<<<16, 256>>>();
    gather_kernel<<<NPAIR, 256>>>(x);

    // expert gate/up + SwiGLU:  h = silu(xg @ wg_e) * (xg @ wu_e)
    gateup_gemm<<<dim3((HDIM+BN-1)/BN, NPAIR/BM, NEXP), 256>>>(
        p_xg, CDIM, wg, wu, (size_t)CDIM*HDIM, p_h, p_off, p_cnt, CDIM);
    // shared gate/up
    gateup_gemm<<<dim3((HDIM+BN-1)/BN, TK/BM, 1), 256>>>(
        x, CDIM, sg, su, 0, p_hs, p_soff, p_scnt, CDIM);

    // expert down:  yd = (h @ wd_e) * router_weight
    down_gemm<<<dim3(CDIM/BN, NPAIR/BM, NEXP), 256>>>(
        p_h, HDIM, wd, (size_t)HDIM*CDIM, p_yd, p_pw, p_off, p_cnt, HDIM, CDIM);
    // shared down
    down_gemm<<<dim3(CDIM/BN, TK/BM, 1), 256>>>(
        p_hs, HDIM, sd, 0, p_ys, nullptr, p_soff, p_scnt, HDIM, CDIM);

    combine_kernel<<<TK, 256>>>(out);

    if (out_size > TK * CDIM)
        aux_kernel<<<1, 1>>>(out + (size_t)TK * CDIM);
}

// round 6
// speedup vs baseline: 1.4974x; 1.4972x over previous
#include <cuda_runtime.h>
#include <cuda_bf16.h>
#include <math.h>
#include <stdint.h>

#define TK    4096
#define CDIM  1024
#define NEXP  8
#define TOPK  2
#define HDIM  2736
#define HPAD  2816
#define NPAIR (TK*TOPK)

typedef __nv_bfloat16 bf16;

// ---------------- PTX helpers ------------------------------------------------
__device__ __forceinline__ uint32_t smem_u32(const void* p) {
    uint32_t a;
    asm("{ .reg .u64 t; cvta.to.shared.u64 t, %1; cvt.u32.u64 %0, t; }"
        : "=r"(a) : "l"(p));
    return a;
}
__device__ __forceinline__ void cpa16(uint32_t d, const void* s) {
    asm volatile("cp.async.cg.shared.global [%0], [%1], 16;" :: "r"(d), "l"(s));
}
#define CP_COMMIT() asm volatile("cp.async.commit_group;" ::: "memory")
#define CP_WAIT1()  asm volatile("cp.async.wait_group 1;" ::: "memory")
#define CP_WAIT0()  asm volatile("cp.async.wait_group 0;" ::: "memory")

__device__ __forceinline__ void ldsm4(uint32_t* r, uint32_t a) {
    asm volatile("ldmatrix.sync.aligned.m8n8.x4.shared.b16 {%0,%1,%2,%3}, [%4];"
        : "=r"(r[0]), "=r"(r[1]), "=r"(r[2]), "=r"(r[3]) : "r"(a));
}
// non-trans x2: B stored [N][K] already matches col-major (k,n) fragment
__device__ __forceinline__ void ldsm2(uint32_t* r, uint32_t a) {
    asm volatile("ldmatrix.sync.aligned.m8n8.x2.shared.b16 {%0,%1}, [%2];"
        : "=r"(r[0]), "=r"(r[1]) : "r"(a));
}
__device__ __forceinline__ void mma16816(float* d, const uint32_t* a, const uint32_t* b) {
    asm volatile("mma.sync.aligned.m16n8k16.row.col.f32.bf16.bf16.f32 "
        "{%0,%1,%2,%3}, {%4,%5,%6,%7}, {%8,%9}, {%0,%1,%2,%3};"
        : "+f"(d[0]), "+f"(d[1]), "+f"(d[2]), "+f"(d[3])
        : "r"(a[0]), "r"(a[1]), "r"(a[2]), "r"(a[3]), "r"(b[0]), "r"(b[1]));
}

// ---------------- scratch ----------------------------------------------------
__device__ int   g_cnt[NEXP];
__device__ int   g_off[NEXP];
__device__ int   g_cur[NEXP];
__device__ float g_psum[NEXP];
__device__ int   g_soff[1];
__device__ int   g_scnt[1];
__device__ int   g_top_i[TK*TOPK];
__device__ float g_top_w[TK*TOPK];
__device__ int   g_perm[NPAIR];
__device__ float g_pw[NPAIR];
__device__ int   g_pos[TK*TOPK];

__device__ __align__(256) bf16 g_xgh[(size_t)NPAIR*CDIM];
__device__ __align__(256) bf16 g_xgl[(size_t)NPAIR*CDIM];
__device__ __align__(256) bf16 g_xsh[(size_t)TK*CDIM];
__device__ __align__(256) bf16 g_xsl[(size_t)TK*CDIM];
__device__ __align__(256) bf16 g_wgTh[(size_t)NEXP*HPAD*CDIM];
__device__ __align__(256) bf16 g_wgTl[(size_t)NEXP*HPAD*CDIM];
__device__ __align__(256) bf16 g_wuTh[(size_t)NEXP*HPAD*CDIM];
__device__ __align__(256) bf16 g_wuTl[(size_t)NEXP*HPAD*CDIM];
__device__ __align__(256) bf16 g_wdTh[(size_t)NEXP*CDIM*HPAD];
__device__ __align__(256) bf16 g_wdTl[(size_t)NEXP*CDIM*HPAD];
__device__ __align__(256) bf16 g_sgTh[(size_t)HPAD*CDIM];
__device__ __align__(256) bf16 g_sgTl[(size_t)HPAD*CDIM];
__device__ __align__(256) bf16 g_suTh[(size_t)HPAD*CDIM];
__device__ __align__(256) bf16 g_suTl[(size_t)HPAD*CDIM];
__device__ __align__(256) bf16 g_sdTh[(size_t)CDIM*HPAD];
__device__ __align__(256) bf16 g_sdTl[(size_t)CDIM*HPAD];
__device__ __align__(256) bf16 g_hh[(size_t)NPAIR*HPAD];
__device__ __align__(256) bf16 g_hl[(size_t)NPAIR*HPAD];
__device__ __align__(256) bf16 g_hsh[(size_t)TK*HPAD];
__device__ __align__(256) bf16 g_hsl[(size_t)TK*HPAD];
__device__ __align__(256) float g_yd[(size_t)NPAIR*CDIM];
__device__ __align__(256) float g_ys[(size_t)TK*CDIM];

// ---------------- small kernels ----------------------------------------------
__global__ void zero_kernel() {
    int t = threadIdx.x;
    if (t < NEXP) { g_cnt[t] = 0; g_psum[t] = 0.f; }
}

__global__ void router_kernel(const float* __restrict__ x,
                              const float* __restrict__ rw) {
    int warp = threadIdx.x >> 5, lane = threadIdx.x & 31;
    int t = blockIdx.x * (blockDim.x >> 5) + warp;
    if (t >= TK) return;
    const float* xr = x + (size_t)t * CDIM;
    float acc[NEXP];
#pragma unroll
    for (int e = 0; e < NEXP; e++) acc[e] = 0.f;
    for (int c = lane; c < CDIM; c += 32) {
        float xv = xr[c];
        const float4* rp = (const float4*)(rw + (size_t)c * NEXP);
        float4 r0 = rp[0], r1 = rp[1];
        acc[0] += xv*r0.x; acc[1] += xv*r0.y; acc[2] += xv*r0.z; acc[3] += xv*r0.w;
        acc[4] += xv*r1.x; acc[5] += xv*r1.y; acc[6] += xv*r1.z; acc[7] += xv*r1.w;
    }
#pragma unroll
    for (int e = 0; e < NEXP; e++)
#pragma unroll
        for (int s = 16; s; s >>= 1)
            acc[e] += __shfl_xor_sync(0xffffffffu, acc[e], s);
    if (lane == 0) {
        int i0 = 0; float v0 = acc[0];
#pragma unroll
        for (int e = 1; e < NEXP; e++) if (acc[e] > v0) { v0 = acc[e]; i0 = e; }
        int i1 = -1; float v1 = -INFINITY;
#pragma unroll
        for (int e = 0; e < NEXP; e++)
            if (e != i0 && acc[e] > v1) { v1 = acc[e]; i1 = e; }
        float w0 = 1.f / (1.f + expf(v1 - v0));
        g_top_i[t*2+0] = i0; g_top_i[t*2+1] = i1;
        g_top_w[t*2+0] = w0; g_top_w[t*2+1] = 1.f - w0;
        atomicAdd(&g_cnt[i0], 1); atomicAdd(&g_cnt[i1], 1);
        float s = 0.f, pe[NEXP];
#pragma unroll
        for (int e = 0; e < NEXP; e++) { pe[e] = expf(acc[e] - v0); s += pe[e]; }
        float inv = 1.f / s;
#pragma unroll
        for (int e = 0; e < NEXP; e++) atomicAdd(&g_psum[e], pe[e] * inv);
    }
}

__global__ void offsets_kernel() {
    int o = 0;
    for (int e = 0; e < NEXP; e++) { g_off[e] = o; g_cur[e] = o; o += g_cnt[e]; }
    g_soff[0] = 0; g_scnt[0] = TK;
}

__global__ void scatter_kernel() {
    int t = blockIdx.x * blockDim.x + threadIdx.x;
    if (t >= TK) return;
#pragma unroll
    for (int k = 0; k < TOPK; k++) {
        int e = g_top_i[t*2+k];
        int pos = atomicAdd(&g_cur[e], 1);
        g_perm[pos] = t;
        g_pw[pos]   = g_top_w[t*2+k];
        g_pos[t*2+k] = pos;
    }
}

__device__ __forceinline__ uint32_t pack2(bf16 a, bf16 b) {
    __nv_bfloat162 t = __halves2bfloat162(a, b);
    return *reinterpret_cast<uint32_t*>(&t);
}
__device__ __forceinline__ void split2(float a, float b, uint32_t& hi, uint32_t& lo) {
    bf16 ha = __float2bfloat16(a), hb = __float2bfloat16(b);
    bf16 la = __float2bfloat16(a - __bfloat162float(ha));
    bf16 lb = __float2bfloat16(b - __bfloat162float(hb));
    hi = pack2(ha, hb); lo = pack2(la, lb);
}

__global__ void gather_split(const float* __restrict__ x) {
    int p = blockIdx.x;
    int src = g_perm[p];
    float4 v = ((const float4*)(x + (size_t)src * CDIM))[threadIdx.x];
    uint2 h, l;
    split2(v.x, v.y, h.x, l.x);
    split2(v.z, v.w, h.y, l.y);
    ((uint2*)(g_xgh + (size_t)p * CDIM))[threadIdx.x] = h;
    ((uint2*)(g_xgl + (size_t)p * CDIM))[threadIdx.x] = l;
}

__global__ void xsplit(const float* __restrict__ x) {
    int t = blockIdx.x;
    float4 v = ((const float4*)(x + (size_t)t * CDIM))[threadIdx.x];
    uint2 h, l;
    split2(v.x, v.y, h.x, l.x);
    split2(v.z, v.w, h.y, l.y);
    ((uint2*)(g_xsh + (size_t)t * CDIM))[threadIdx.x] = h;
    ((uint2*)(g_xsl + (size_t)t * CDIM))[threadIdx.x] = l;
}

// transpose+split: in [K,N] fp32 -> out [Npad rows][Kpad cols] bf16 hi/lo
__global__ void tsplit(const float* __restrict__ in, int K, int N, size_t in_bs,
                       bf16* __restrict__ oh, bf16* __restrict__ ol,
                       int Kpad, size_t out_bs) {
    __shared__ float t[32][33];
    int b = blockIdx.z;
    in += (size_t)b * in_bs; oh += (size_t)b * out_bs; ol += (size_t)b * out_bs;
    int nb = blockIdx.x * 32, kb = blockIdx.y * 32;
    int tx = threadIdx.x, ty = threadIdx.y;
#pragma unroll
    for (int i = 0; i < 4; i++) {
        int k = kb + ty + i*8, n = nb + tx;
        t[ty + i*8][tx] = (k < K && n < N) ? in[(size_t)k * N + n] : 0.f;
    }
    __syncthreads();
#pragma unroll
    for (int i = 0; i < 4; i++) {
        int n = nb + ty + i*8, k = kb + tx;
        float v = t[tx][ty + i*8];
        bf16 h = __float2bfloat16(v);
        oh[(size_t)n * Kpad + k] = h;
        ol[(size_t)n * Kpad + k] = __float2bfloat16(v - __bfloat162float(h));
    }
}

// ---------------- tile loader: rows x 32 bf16 cols, 80B row stride -----------
__device__ __forceinline__ void ld_tile(uint32_t dst, const bf16* __restrict__ g,
                                        int ldg, int rbase, int clampv, int kc,
                                        int rows, int tid) {
    int chunks = rows * 4;
    for (int c = tid; c < chunks; c += 512) {
        int r = c >> 2, cb = (c & 3) << 4;
        int row = rbase + r; if (row > clampv) row = clampv;
        cpa16(dst + (uint32_t)r * 80u + cb,
              (const char*)(g + (size_t)row * ldg + kc) + cb);
    }
}

#define STAGE_B 61440u

// ---------------- gate/up GEMM + SwiGLU (CTA 256x64, 16 warps 8x2) -----------
__global__ void __launch_bounds__(512, 1)
gateup_mma(const bf16* __restrict__ Ah, const bf16* __restrict__ Al, int ldA,
           const bf16* __restrict__ BGh, const bf16* __restrict__ BGl,
           const bf16* __restrict__ BUh, const bf16* __restrict__ BUl,
           size_t bestride, bf16* __restrict__ Hh, bf16* __restrict__ Hl,
           const int* __restrict__ offs, const int* __restrict__ cnts)
{
    extern __shared__ __align__(256) char smem[];
    int e = blockIdx.z;
    int off = offs[e], cnt = cnts[e];
    int row0 = off + blockIdx.y * 256, rowEnd = off + cnt;
    if (row0 >= rowEnd) return;
    int clampA = rowEnd - 1;
    int n0 = blockIdx.x * 64;
    const bf16* bgh = BGh + (size_t)e * bestride;
    const bf16* bgl = BGl + (size_t)e * bestride;
    const bf16* buh = BUh + (size_t)e * bestride;
    const bf16* bul = BUl + (size_t)e * bestride;

    uint32_t SB = smem_u32(smem);
    int tid = threadIdx.x, wid = tid >> 5, lane = tid & 31;
    int wm = wid >> 1, wn = wid & 1;

    float accg[2][4][4], accu[2][4][4];
#pragma unroll
    for (int a = 0; a < 2; a++)
#pragma unroll
        for (int b = 0; b < 4; b++)
#pragma unroll
            for (int c = 0; c < 4; c++) { accg[a][b][c] = 0.f; accu[a][b][c] = 0.f; }

    uint32_t aoff = (uint32_t)(wm*32 + (lane & 15)) * 80u + ((lane & 16) ? 16u : 0u);
    uint32_t boff = (uint32_t)(wn*32 + (lane & 7))  * 80u + ((lane & 8)  ? 16u : 0u);

    const int NCH = CDIM / 32;  // 32
#pragma unroll 1
    for (int i = 0; i < 2; i++) {
        uint32_t st = SB + (uint32_t)i * STAGE_B;
        int kc = i * 32;
        ld_tile(st +     0, Ah,  ldA,  row0, clampA,     kc, 256, tid);
        ld_tile(st + 20480, Al,  ldA,  row0, clampA,     kc, 256, tid);
        ld_tile(st + 40960, bgh, CDIM, n0,   0x7fffffff, kc, 64, tid);
        ld_tile(st + 46080, bgl, CDIM, n0,   0x7fffffff, kc, 64, tid);
        ld_tile(st + 51200, buh, CDIM, n0,   0x7fffffff, kc, 64, tid);
        ld_tile(st + 56320, bul, CDIM, n0,   0x7fffffff, kc, 64, tid);
        CP_COMMIT();
    }
#pragma unroll 1
    for (int i = 0; i < NCH; i++) {
        uint32_t st = SB + (uint32_t)(i & 1) * STAGE_B;
        if (i + 2 < NCH) { CP_WAIT1(); } else { CP_WAIT0(); }
        __syncthreads();
#pragma unroll
        for (int ks = 0; ks < 2; ks++) {
            uint32_t kb = ks * 32;
            uint32_t ah2[2][4], al2[2][4];
            ldsm4(ah2[0], st + aoff + kb);
            ldsm4(ah2[1], st + aoff + 1280 + kb);
            ldsm4(al2[0], st + 20480 + aoff + kb);
            ldsm4(al2[1], st + 20480 + aoff + 1280 + kb);
            uint32_t bh[4][2], bl[4][2];
#pragma unroll
            for (int nt = 0; nt < 4; nt++) {
                ldsm2(bh[nt], st + 40960 + boff + nt*640 + kb);
                ldsm2(bl[nt], st + 46080 + boff + nt*640 + kb);
            }
#pragma unroll
            for (int mt = 0; mt < 2; mt++)
#pragma unroll
                for (int nt = 0; nt < 4; nt++) {
                    mma16816(accg[mt][nt], ah2[mt], bh[nt]);
                    mma16816(accg[mt][nt], ah2[mt], bl[nt]);
                    mma16816(accg[mt][nt], al2[mt], bh[nt]);
                }
#pragma unroll
            for (int nt = 0; nt < 4; nt++) {
                ldsm2(bh[nt], st + 51200 + boff + nt*640 + kb);
                ldsm2(bl[nt], st + 56320 + boff + nt*640 + kb);
            }
#pragma unroll
            for (int mt = 0; mt < 2; mt++)
#pragma unroll
                for (int nt = 0; nt < 4; nt++) {
                    mma16816(accu[mt][nt], ah2[mt], bh[nt]);
                    mma16816(accu[mt][nt], ah2[mt], bl[nt]);
                    mma16816(accu[mt][nt], al2[mt], bh[nt]);
                }
        }
        __syncthreads();
        if (i + 2 < NCH) {
            int kc = (i + 2) * 32;
            ld_tile(st +     0, Ah,  ldA,  row0, clampA,     kc, 256, tid);
            ld_tile(st + 20480, Al,  ldA,  row0, clampA,     kc, 256, tid);
            ld_tile(st + 40960, bgh, CDIM, n0,   0x7fffffff, kc, 64, tid);
            ld_tile(st + 46080, bgl, CDIM, n0,   0x7fffffff, kc, 64, tid);
            ld_tile(st + 51200, buh, CDIM, n0,   0x7fffffff, kc, 64, tid);
            ld_tile(st + 56320, bul, CDIM, n0,   0x7fffffff, kc, 64, tid);
            CP_COMMIT();
        }
    }

    // epilogue: h = silu(g)*u -> bf16 hi/lo
    int gid = lane >> 2, t2 = (lane & 3) * 2;
    int colb = n0 + wn*32 + t2;
#pragma unroll
    for (int mt = 0; mt < 2; mt++) {
        int rbase = row0 + wm*32 + mt*16;
#pragma unroll
        for (int hf = 0; hf < 2; hf++) {
            int r = rbase + gid + hf*8;
            if (r < rowEnd) {
                size_t ro = (size_t)r * HPAD + colb;
#pragma unroll
                for (int nt = 0; nt < 4; nt++) {
                    float g0 = accg[mt][nt][hf*2+0], g1 = accg[mt][nt][hf*2+1];
                    float u0 = accu[mt][nt][hf*2+0], u1 = accu[mt][nt][hf*2+1];
                    float h0 = g0 / (1.f + expf(-g0)) * u0;
                    float h1 = g1 / (1.f + expf(-g1)) * u1;
                    uint32_t ph, pl;
                    split2(h0, h1, ph, pl);
                    *(uint32_t*)(Hh + ro + nt*8) = ph;
                    *(uint32_t*)(Hl + ro + nt*8) = pl;
                }
            }
        }
    }
}

// ---------------- down GEMM (CTA 256x128, 16 warps 4x4) ----------------------
__global__ void __launch_bounds__(512, 1)
down_mma(const bf16* __restrict__ Ah, const bf16* __restrict__ Al, int ldA,
         const bf16* __restrict__ Bh, const bf16* __restrict__ Bl,
         size_t bestride, float* __restrict__ Y, const float* __restrict__ scale,
         const int* __restrict__ offs, const int* __restrict__ cnts)
{
    extern __shared__ __align__(256) char smem[];
    int e = blockIdx.z;
    int off = offs[e], cnt = cnts[e];
    int row0 = off + blockIdx.y * 256, rowEnd = off + cnt;
    if (row0 >= rowEnd) return;
    int clampA = rowEnd - 1;
    int n0 = blockIdx.x * 128;
    const bf16* bh_g = Bh + (size_t)e * bestride;
    const bf16* bl_g = Bl + (size_t)e * bestride;

    uint32_t SB = smem_u32(smem);
    int tid = threadIdx.x, wid = tid >> 5, lane = tid & 31;
    int wm = wid >> 2, wn = wid & 3;

    float acc[4][4][4];
#pragma unroll
    for (int a = 0; a < 4; a++)
#pragma unroll
        for (int b = 0; b < 4; b++)
#pragma unroll
            for (int c = 0; c < 4; c++) acc[a][b][c] = 0.f;

    uint32_t aoff = (uint32_t)(wm*64 + (lane & 15)) * 80u + ((lane & 16) ? 16u : 0u);
    uint32_t boff = (uint32_t)(wn*32 + (lane & 7))  * 80u + ((lane & 8)  ? 16u : 0u);

    const int NCH = HPAD / 32;  // 88
#pragma unroll 1
    for (int i = 0; i < 2; i++) {
        uint32_t st = SB + (uint32_t)i * STAGE_B;
        int kc = i * 32;
        ld_tile(st +     0, Ah,   ldA,  row0, clampA,     kc, 256, tid);
        ld_tile(st + 20480, Al,   ldA,  row0, clampA,     kc, 256, tid);
        ld_tile(st + 40960, bh_g, HPAD, n0,   0x7fffffff, kc, 128, tid);
        ld_tile(st + 51200, bl_g, HPAD, n0,   0x7fffffff, kc, 128, tid);
        CP_COMMIT();
    }
#pragma unroll 1
    for (int i = 0; i < NCH; i++) {
        uint32_t st = SB + (uint32_t)(i & 1) * STAGE_B;
        if (i + 2 < NCH) { CP_WAIT1(); } else { CP_WAIT0(); }
        __syncthreads();
#pragma unroll
        for (int ks = 0; ks < 2; ks++) {
            uint32_t kb = ks * 32;
            uint32_t ah2[4][4], al2[4][4];
#pragma unroll
            for (int mt = 0; mt < 4; mt++) {
                ldsm4(ah2[mt], st + aoff + mt*1280 + kb);
                ldsm4(al2[mt], st + 20480 + aoff + mt*1280 + kb);
            }
#pragma unroll
            for (int nt = 0; nt < 4; nt++) {
                uint32_t bh[2], bl[2];
                ldsm2(bh, st + 40960 + boff + nt*640 + kb);
                ldsm2(bl, st + 51200 + boff + nt*640 + kb);
#pragma unroll
                for (int mt = 0; mt < 4; mt++) {
                    mma16816(acc[mt][nt], ah2[mt], bh);
                    mma16816(acc[mt][nt], ah2[mt], bl);
                    mma16816(acc[mt][nt], al2[mt], bh);
                }
            }
        }
        __syncthreads();
        if (i + 2 < NCH) {
            int kc = (i + 2) * 32;
            ld_tile(st +     0, Ah,   ldA,  row0, clampA,     kc, 256, tid);
            ld_tile(st + 20480, Al,   ldA,  row0, clampA,     kc, 256, tid);
            ld_tile(st + 40960, bh_g, HPAD, n0,   0x7fffffff, kc, 128, tid);
            ld_tile(st + 51200, bl_g, HPAD, n0,   0x7fffffff, kc, 128, tid);
            CP_COMMIT();
        }
    }

    int gid = lane >> 2, t2 = (lane & 3) * 2;
    int colb = n0 + wn*32 + t2;
#pragma unroll
    for (int mt = 0; mt < 4; mt++) {
        int rbase = row0 + wm*64 + mt*16;
#pragma unroll
        for (int hf = 0; hf < 2; hf++) {
            int r = rbase + gid + hf*8;
            if (r < rowEnd) {
                float sc = scale ? scale[r] : 1.f;
                float* yp = Y + (size_t)r * CDIM + colb;
#pragma unroll
                for (int nt = 0; nt < 4; nt++) {
                    float2 v;
                    v.x = acc[mt][nt][hf*2+0] * sc;
                    v.y = acc[mt][nt][hf*2+1] * sc;
                    *(float2*)(yp + nt*8) = v;
                }
            }
        }
    }
}

// ---------------- combine / aux ----------------------------------------------
__global__ void combine_kernel(float* __restrict__ out) {
    int t = blockIdx.x;
    int p0 = g_pos[t*2+0], p1 = g_pos[t*2+1];
    const float4* a = (const float4*)(g_yd + (size_t)p0 * CDIM);
    const float4* b = (const float4*)(g_yd + (size_t)p1 * CDIM);
    const float4* c = (const float4*)(g_ys + (size_t)t  * CDIM);
    float4* o = (float4*)(out + (size_t)t * CDIM);
    int i = threadIdx.x;
    float4 va = a[i], vb = b[i], vc = c[i];
    o[i] = make_float4(va.x+vb.x+vc.x, va.y+vb.y+vc.y,
                       va.z+vb.z+vc.z, va.w+vb.w+vc.w);
}

__global__ void aux_kernel(float* __restrict__ dst) {
    float a = 0.f;
    for (int e = 0; e < NEXP; e++) {
        float f = (float)g_cnt[e] / (float)(TK * TOPK);
        float p = g_psum[e] / (float)TK;
        a += f * p;
    }
    dst[0] = (float)NEXP * a;
}

// ---------------- launch -----------------------------------------------------
extern "C" void kernel_launch(void* const* d_in, const int* in_sizes, int n_in,
                              void* d_out, int out_size) {
    const float* x  = (const float*)d_in[0];
    const float* rw = (const float*)d_in[1];
    const float* wg = (const float*)d_in[2];
    const float* wu = (const float*)d_in[3];
    const float* wd = (const float*)d_in[4];
    const float* sg = (const float*)d_in[5];
    const float* su = (const float*)d_in[6];
    const float* sd = (const float*)d_in[7];
    float* out = (float*)d_out;

    cudaFuncSetAttribute(gateup_mma, cudaFuncAttributeMaxDynamicSharedMemorySize,
                         2 * STAGE_B);
    cudaFuncSetAttribute(down_mma, cudaFuncAttributeMaxDynamicSharedMemorySize,
                         2 * STAGE_B);

    bf16 *p_xgh, *p_xgl, *p_xsh, *p_xsl;
    bf16 *p_wgTh, *p_wgTl, *p_wuTh, *p_wuTl, *p_wdTh, *p_wdTl;
    bf16 *p_sgTh, *p_sgTl, *p_suTh, *p_suTl, *p_sdTh, *p_sdTl;
    bf16 *p_hh, *p_hl, *p_hsh, *p_hsl;
    float *p_yd, *p_ys, *p_pw;
    int *p_off, *p_cnt, *p_soff, *p_scnt;
    cudaGetSymbolAddress((void**)&p_xgh, g_xgh);
    cudaGetSymbolAddress((void**)&p_xgl, g_xgl);
    cudaGetSymbolAddress((void**)&p_xsh, g_xsh);
    cudaGetSymbolAddress((void**)&p_xsl, g_xsl);
    cudaGetSymbolAddress((void**)&p_wgTh, g_wgTh);
    cudaGetSymbolAddress((void**)&p_wgTl, g_wgTl);
    cudaGetSymbolAddress((void**)&p_wuTh, g_wuTh);
    cudaGetSymbolAddress((void**)&p_wuTl, g_wuTl);
    cudaGetSymbolAddress((void**)&p_wdTh, g_wdTh);
    cudaGetSymbolAddress((void**)&p_wdTl, g_wdTl);
    cudaGetSymbolAddress((void**)&p_sgTh, g_sgTh);
    cudaGetSymbolAddress((void**)&p_sgTl, g_sgTl);
    cudaGetSymbolAddress((void**)&p_suTh, g_suTh);
    cudaGetSymbolAddress((void**)&p_suTl, g_suTl);
    cudaGetSymbolAddress((void**)&p_sdTh, g_sdTh);
    cudaGetSymbolAddress((void**)&p_sdTl, g_sdTl);
    cudaGetSymbolAddress((void**)&p_hh, g_hh);
    cudaGetSymbolAddress((void**)&p_hl, g_hl);
    cudaGetSymbolAddress((void**)&p_hsh, g_hsh);
    cudaGetSymbolAddress((void**)&p_hsl, g_hsl);
    cudaGetSymbolAddress((void**)&p_yd, g_yd);
    cudaGetSymbolAddress((void**)&p_ys, g_ys);
    cudaGetSymbolAddress((void**)&p_pw, g_pw);
    cudaGetSymbolAddress((void**)&p_off, g_off);
    cudaGetSymbolAddress((void**)&p_cnt, g_cnt);
    cudaGetSymbolAddress((void**)&p_soff, g_soff);
    cudaGetSymbolAddress((void**)&p_scnt, g_scnt);

    zero_kernel<<<1, 32>>>();
    router_kernel<<<TK/4, 128>>>(x, rw);
    offsets_kernel<<<1, 1>>>();
    scatter_kernel<<<16, 256>>>();

    gather_split<<<NPAIR, 256>>>(x);
    xsplit<<<TK, 256>>>(x);

    dim3 tb(32, 8);
    tsplit<<<dim3(HPAD/32, CDIM/32, NEXP), tb>>>(wg, CDIM, HDIM,
        (size_t)CDIM*HDIM, p_wgTh, p_wgTl, CDIM, (size_t)HPAD*CDIM);
    tsplit<<<dim3(HPAD/32, CDIM/32, NEXP), tb>>>(wu, CDIM, HDIM,
        (size_t)CDIM*HDIM, p_wuTh, p_wuTl, CDIM, (size_t)HPAD*CDIM);
    tsplit<<<dim3(CDIM/32, HPAD/32, NEXP), tb>>>(wd, HDIM, CDIM,
        (size_t)HDIM*CDIM, p_wdTh, p_wdTl, HPAD, (size_t)CDIM*HPAD);
    tsplit<<<dim3(HPAD/32, CDIM/32, 1), tb>>>(sg, CDIM, HDIM,
        0, p_sgTh, p_sgTl, CDIM, 0);
    tsplit<<<dim3(HPAD/32, CDIM/32, 1), tb>>>(su, CDIM, HDIM,
        0, p_suTh, p_suTl, CDIM, 0);
    tsplit<<<dim3(CDIM/32, HPAD/32, 1), tb>>>(sd, HDIM, CDIM,
        0, p_sdTh, p_sdTl, HPAD, 0);

    // expert gate/up + SwiGLU
    gateup_mma<<<dim3(HPAD/64, NPAIR/256, NEXP), 512, 2*STAGE_B>>>(
        p_xgh, p_xgl, CDIM, p_wgTh, p_wgTl, p_wuTh, p_wuTl,
        (size_t)HPAD*CDIM, p_hh, p_hl, p_off, p_cnt);
    // shared gate/up
    gateup_mma<<<dim3(HPAD/64, TK/256, 1), 512, 2*STAGE_B>>>(
        p_xsh, p_xsl, CDIM, p_sgTh, p_sgTl, p_suTh, p_suTl,
        0, p_hsh, p_hsl, p_soff, p_scnt);

    // expert down (router-weight scaled)
    down_mma<<<dim3(CDIM/128, NPAIR/256, NEXP), 512, 2*STAGE_B>>>(
        p_hh, p_hl, HPAD, p_wdTh, p_wdTl, (size_t)CDIM*HPAD,
        p_yd, p_pw, p_off, p_cnt);
    // shared down
    down_mma<<<dim3(CDIM/128, TK/256, 1), 512, 2*STAGE_B>>>(
        p_hsh, p_hsl, HPAD, p_sdTh, p_sdTl, 0,
        p_ys, nullptr, p_soff, p_scnt);

    combine_kernel<<<TK, 256>>>(out);

    if (out_size > TK * CDIM)
        aux_kernel<<<1, 1>>>(out + (size_t)TK * CDIM);
}

// round 7
// speedup vs baseline: 3.0375x; 2.0286x over previous
#include <cuda_runtime.h>
#include <cuda_fp16.h>
#include <math.h>
#include <stdint.h>

#define TK    4096
#define CDIM  1024
#define NEXP  8
#define TOPK  2
#define HDIM  2736
#define HPAD  2816
#define NPAIR (TK*TOPK)

typedef __half hf;

// ---------------- PTX helpers ------------------------------------------------
__device__ __forceinline__ uint32_t smem_u32(const void* p) {
    uint32_t a;
    asm("{ .reg .u64 t; cvta.to.shared.u64 t, %1; cvt.u32.u64 %0, t; }"
        : "=r"(a) : "l"(p));
    return a;
}
__device__ __forceinline__ void cpa16(uint32_t d, const void* s) {
    asm volatile("cp.async.cg.shared.global [%0], [%1], 16;" :: "r"(d), "l"(s));
}
#define CP_COMMIT() asm volatile("cp.async.commit_group;" ::: "memory")
#define CP_WAIT2()  asm volatile("cp.async.wait_group 2;" ::: "memory")

__device__ __forceinline__ void ldsm4(uint32_t* r, uint32_t a) {
    asm volatile("ldmatrix.sync.aligned.m8n8.x4.shared.b16 {%0,%1,%2,%3}, [%4];"
        : "=r"(r[0]), "=r"(r[1]), "=r"(r[2]), "=r"(r[3]) : "r"(a));
}
__device__ __forceinline__ void mma16816(float* d, const uint32_t* a, const uint32_t* b) {
    asm volatile("mma.sync.aligned.m16n8k16.row.col.f32.f16.f16.f32 "
        "{%0,%1,%2,%3}, {%4,%5,%6,%7}, {%8,%9}, {%0,%1,%2,%3};"
        : "+f"(d[0]), "+f"(d[1]), "+f"(d[2]), "+f"(d[3])
        : "r"(a[0]), "r"(a[1]), "r"(a[2]), "r"(a[3]), "r"(b[0]), "r"(b[1]));
}

// ---------------- scratch ----------------------------------------------------
__device__ int   g_cnt[NEXP];
__device__ int   g_off[NEXP];
__device__ int   g_cur[NEXP];
__device__ float g_psum[NEXP];
__device__ int   g_soff[1];
__device__ int   g_scnt[1];
__device__ int   g_top_i[TK*TOPK];
__device__ float g_top_w[TK*TOPK];
__device__ int   g_perm[NPAIR];
__device__ float g_pw[NPAIR];
__device__ int   g_pos[TK*TOPK];

__device__ __align__(256) hf g_xg[(size_t)NPAIR*CDIM];     // gathered x (fp16)
__device__ __align__(256) hf g_xs[(size_t)TK*CDIM];        // x for shared (fp16)
__device__ __align__(256) hf g_wgTh[(size_t)NEXP*HPAD*CDIM];
__device__ __align__(256) hf g_wgTl[(size_t)NEXP*HPAD*CDIM];
__device__ __align__(256) hf g_wuTh[(size_t)NEXP*HPAD*CDIM];
__device__ __align__(256) hf g_wuTl[(size_t)NEXP*HPAD*CDIM];
__device__ __align__(256) hf g_wdTh[(size_t)NEXP*CDIM*HPAD];
__device__ __align__(256) hf g_wdTl[(size_t)NEXP*CDIM*HPAD];
__device__ __align__(256) hf g_sgTh[(size_t)HPAD*CDIM];
__device__ __align__(256) hf g_sgTl[(size_t)HPAD*CDIM];
__device__ __align__(256) hf g_suTh[(size_t)HPAD*CDIM];
__device__ __align__(256) hf g_suTl[(size_t)HPAD*CDIM];
__device__ __align__(256) hf g_sdTh[(size_t)CDIM*HPAD];
__device__ __align__(256) hf g_sdTl[(size_t)CDIM*HPAD];
__device__ __align__(256) hf g_h [(size_t)NPAIR*HPAD];     // expert hidden (fp16)
__device__ __align__(256) hf g_hs[(size_t)TK*HPAD];        // shared hidden (fp16)
__device__ __align__(256) float g_yd[(size_t)NPAIR*CDIM];
__device__ __align__(256) float g_ys[(size_t)TK*CDIM];

// ---------------- small kernels ----------------------------------------------
__global__ void zero_kernel() {
    int t = threadIdx.x;
    if (t < NEXP) { g_cnt[t] = 0; g_psum[t] = 0.f; }
}

__global__ void router_kernel(const float* __restrict__ x,
                              const float* __restrict__ rw) {
    int warp = threadIdx.x >> 5, lane = threadIdx.x & 31;
    int t = blockIdx.x * (blockDim.x >> 5) + warp;
    if (t >= TK) return;
    const float* xr = x + (size_t)t * CDIM;
    float acc[NEXP];
#pragma unroll
    for (int e = 0; e < NEXP; e++) acc[e] = 0.f;
    for (int c = lane; c < CDIM; c += 32) {
        float xv = xr[c];
        const float4* rp = (const float4*)(rw + (size_t)c * NEXP);
        float4 r0 = rp[0], r1 = rp[1];
        acc[0] += xv*r0.x; acc[1] += xv*r0.y; acc[2] += xv*r0.z; acc[3] += xv*r0.w;
        acc[4] += xv*r1.x; acc[5] += xv*r1.y; acc[6] += xv*r1.z; acc[7] += xv*r1.w;
    }
#pragma unroll
    for (int e = 0; e < NEXP; e++)
#pragma unroll
        for (int s = 16; s; s >>= 1)
            acc[e] += __shfl_xor_sync(0xffffffffu, acc[e], s);
    if (lane == 0) {
        int i0 = 0; float v0 = acc[0];
#pragma unroll
        for (int e = 1; e < NEXP; e++) if (acc[e] > v0) { v0 = acc[e]; i0 = e; }
        int i1 = -1; float v1 = -INFINITY;
#pragma unroll
        for (int e = 0; e < NEXP; e++)
            if (e != i0 && acc[e] > v1) { v1 = acc[e]; i1 = e; }
        float w0 = 1.f / (1.f + expf(v1 - v0));
        g_top_i[t*2+0] = i0; g_top_i[t*2+1] = i1;
        g_top_w[t*2+0] = w0; g_top_w[t*2+1] = 1.f - w0;
        atomicAdd(&g_cnt[i0], 1); atomicAdd(&g_cnt[i1], 1);
        float s = 0.f, pe[NEXP];
#pragma unroll
        for (int e = 0; e < NEXP; e++) { pe[e] = expf(acc[e] - v0); s += pe[e]; }
        float inv = 1.f / s;
#pragma unroll
        for (int e = 0; e < NEXP; e++) atomicAdd(&g_psum[e], pe[e] * inv);
    }
}

__global__ void offsets_kernel() {
    int o = 0;
    for (int e = 0; e < NEXP; e++) { g_off[e] = o; g_cur[e] = o; o += g_cnt[e]; }
    g_soff[0] = 0; g_scnt[0] = TK;
}

__global__ void scatter_kernel() {
    int t = blockIdx.x * blockDim.x + threadIdx.x;
    if (t >= TK) return;
#pragma unroll
    for (int k = 0; k < TOPK; k++) {
        int e = g_top_i[t*2+k];
        int pos = atomicAdd(&g_cur[e], 1);
        g_perm[pos] = t;
        g_pw[pos]   = g_top_w[t*2+k];
        g_pos[t*2+k] = pos;
    }
}

__device__ __forceinline__ uint32_t packh2(float a, float b) {
    __half2 t = __floats2half2_rn(a, b);
    return *reinterpret_cast<uint32_t*>(&t);
}

// gather token rows -> fp16
__global__ void gather_half(const float* __restrict__ x) {
    int p = blockIdx.x;
    int src = g_perm[p];
    float4 v = ((const float4*)(x + (size_t)src * CDIM))[threadIdx.x];
    uint2 h;
    h.x = packh2(v.x, v.y); h.y = packh2(v.z, v.w);
    ((uint2*)(g_xg + (size_t)p * CDIM))[threadIdx.x] = h;
}

__global__ void xhalf(const float* __restrict__ x) {
    int t = blockIdx.x;
    float4 v = ((const float4*)(x + (size_t)t * CDIM))[threadIdx.x];
    uint2 h;
    h.x = packh2(v.x, v.y); h.y = packh2(v.z, v.w);
    ((uint2*)(g_xs + (size_t)t * CDIM))[threadIdx.x] = h;
}

// transpose+split: in [K,N] fp32 -> out [Npad rows][Kpad cols] fp16 hi/lo
__global__ void tsplit(const float* __restrict__ in, int K, int N, size_t in_bs,
                       hf* __restrict__ oh, hf* __restrict__ ol,
                       int Kpad, size_t out_bs) {
    __shared__ float t[32][33];
    int b = blockIdx.z;
    in += (size_t)b * in_bs; oh += (size_t)b * out_bs; ol += (size_t)b * out_bs;
    int nb = blockIdx.x * 32, kb = blockIdx.y * 32;
    int tx = threadIdx.x, ty = threadIdx.y;
#pragma unroll
    for (int i = 0; i < 4; i++) {
        int k = kb + ty + i*8, n = nb + tx;
        t[ty + i*8][tx] = (k < K && n < N) ? in[(size_t)k * N + n] : 0.f;
    }
    __syncthreads();
#pragma unroll
    for (int i = 0; i < 4; i++) {
        int n = nb + ty + i*8, k = kb + tx;
        float v = t[tx][ty + i*8];
        hf h = __float2half_rn(v);
        oh[(size_t)n * Kpad + k] = h;
        ol[(size_t)n * Kpad + k] = __float2half_rn(v - __half2float(h));
    }
}

// ---------------- tile loader: rows x 32 halfs, 80B row stride ---------------
__device__ __forceinline__ void ld_tile(uint32_t dst, const hf* __restrict__ g,
                                        int ldg, int rbase, int clampv, int kc,
                                        int rows, int tid) {
    int chunks = rows * 4;
    for (int c = tid; c < chunks; c += 512) {
        int r = c >> 2, cb = (c & 3) << 4;
        int row = rbase + r; if (row > clampv) row = clampv;
        cpa16(dst + (uint32_t)r * 80u + cb,
              (const char*)(g + (size_t)row * ldg + kc) + cb);
    }
}

#define STAGE_B 40960u
#define NSTAGE  3

// ---------------- gate/up GEMM + SwiGLU (CTA 256x64, 16 warps 8x2) -----------
// A: 256x32 fp16 single @ st+0 (20480B)
// Bgh/Bgl/Buh/Bul: 64x32 each @ st+20480/25600/30720/35840
__global__ void __launch_bounds__(512, 1)
gateup_mma(const hf* __restrict__ A, int ldA,
           const hf* __restrict__ BGh, const hf* __restrict__ BGl,
           const hf* __restrict__ BUh, const hf* __restrict__ BUl,
           size_t bestride, hf* __restrict__ H,
           const int* __restrict__ offs, const int* __restrict__ cnts)
{
    extern __shared__ __align__(256) char smem[];
    int e = blockIdx.z;
    int off = offs[e], cnt = cnts[e];
    int row0 = off + blockIdx.y * 256, rowEnd = off + cnt;
    if (row0 >= rowEnd) return;
    int clampA = rowEnd - 1;
    int n0 = blockIdx.x * 64;
    const hf* bgh = BGh + (size_t)e * bestride;
    const hf* bgl = BGl + (size_t)e * bestride;
    const hf* buh = BUh + (size_t)e * bestride;
    const hf* bul = BUl + (size_t)e * bestride;

    uint32_t SB = smem_u32(smem);
    int tid = threadIdx.x, wid = tid >> 5, lane = tid & 31;
    int wm = wid >> 1, wn = wid & 1;

    float accg[2][4][4], accu[2][4][4];
#pragma unroll
    for (int a = 0; a < 2; a++)
#pragma unroll
        for (int b = 0; b < 4; b++)
#pragma unroll
            for (int c = 0; c < 4; c++) { accg[a][b][c] = 0.f; accu[a][b][c] = 0.f; }

    uint32_t aoff = (uint32_t)(wm*32 + (lane & 15)) * 80u + ((lane & 16) ? 16u : 0u);
    // paired B: lanes 0-15 tile nt, lanes 16-31 tile nt+1 (+640B)
    uint32_t bpo = (uint32_t)(wn*32 + (lane & 7)) * 80u + ((lane & 8) ? 16u : 0u)
                 + ((lane & 16) ? 640u : 0u);

    const int NCH = CDIM / 32;  // 32
#pragma unroll 1
    for (int i = 0; i < NSTAGE; i++) {
        uint32_t st = SB + (uint32_t)i * STAGE_B;
        int kc = i * 32;
        ld_tile(st +     0, A,   ldA,  row0, clampA,     kc, 256, tid);
        ld_tile(st + 20480, bgh, CDIM, n0,   0x7fffffff, kc, 64, tid);
        ld_tile(st + 25600, bgl, CDIM, n0,   0x7fffffff, kc, 64, tid);
        ld_tile(st + 30720, buh, CDIM, n0,   0x7fffffff, kc, 64, tid);
        ld_tile(st + 35840, bul, CDIM, n0,   0x7fffffff, kc, 64, tid);
        CP_COMMIT();
    }
    int sidx = 0;
#pragma unroll 1
    for (int i = 0; i < NCH; i++) {
        uint32_t st = SB + (uint32_t)sidx * STAGE_B;
        CP_WAIT2();
        __syncthreads();
#pragma unroll
        for (int ks = 0; ks < 2; ks++) {
            uint32_t kb = ks * 32;
            uint32_t af[2][4];
            ldsm4(af[0], st + aoff + kb);
            ldsm4(af[1], st + aoff + 1280 + kb);
            uint32_t bgH[4][2], bgL[4][2], buH[4][2], buL[4][2];
            {
                uint32_t tmp[4];
                ldsm4(tmp, st + 20480 + bpo + kb);
                bgH[0][0]=tmp[0]; bgH[0][1]=tmp[1]; bgH[1][0]=tmp[2]; bgH[1][1]=tmp[3];
                ldsm4(tmp, st + 20480 + bpo + 1280 + kb);
                bgH[2][0]=tmp[0]; bgH[2][1]=tmp[1]; bgH[3][0]=tmp[2]; bgH[3][1]=tmp[3];
                ldsm4(tmp, st + 25600 + bpo + kb);
                bgL[0][0]=tmp[0]; bgL[0][1]=tmp[1]; bgL[1][0]=tmp[2]; bgL[1][1]=tmp[3];
                ldsm4(tmp, st + 25600 + bpo + 1280 + kb);
                bgL[2][0]=tmp[0]; bgL[2][1]=tmp[1]; bgL[3][0]=tmp[2]; bgL[3][1]=tmp[3];
                ldsm4(tmp, st + 30720 + bpo + kb);
                buH[0][0]=tmp[0]; buH[0][1]=tmp[1]; buH[1][0]=tmp[2]; buH[1][1]=tmp[3];
                ldsm4(tmp, st + 30720 + bpo + 1280 + kb);
                buH[2][0]=tmp[0]; buH[2][1]=tmp[1]; buH[3][0]=tmp[2]; buH[3][1]=tmp[3];
                ldsm4(tmp, st + 35840 + bpo + kb);
                buL[0][0]=tmp[0]; buL[0][1]=tmp[1]; buL[1][0]=tmp[2]; buL[1][1]=tmp[3];
                ldsm4(tmp, st + 35840 + bpo + 1280 + kb);
                buL[2][0]=tmp[0]; buL[2][1]=tmp[1]; buL[3][0]=tmp[2]; buL[3][1]=tmp[3];
            }
#pragma unroll
            for (int mt = 0; mt < 2; mt++)
#pragma unroll
                for (int nt = 0; nt < 4; nt++) {
                    mma16816(accg[mt][nt], af[mt], bgH[nt]);
                    mma16816(accg[mt][nt], af[mt], bgL[nt]);
                    mma16816(accu[mt][nt], af[mt], buH[nt]);
                    mma16816(accu[mt][nt], af[mt], buL[nt]);
                }
        }
        __syncthreads();
        if (i + NSTAGE < NCH) {
            int kc = (i + NSTAGE) * 32;
            ld_tile(st +     0, A,   ldA,  row0, clampA,     kc, 256, tid);
            ld_tile(st + 20480, bgh, CDIM, n0,   0x7fffffff, kc, 64, tid);
            ld_tile(st + 25600, bgl, CDIM, n0,   0x7fffffff, kc, 64, tid);
            ld_tile(st + 30720, buh, CDIM, n0,   0x7fffffff, kc, 64, tid);
            ld_tile(st + 35840, bul, CDIM, n0,   0x7fffffff, kc, 64, tid);
        }
        CP_COMMIT();
        sidx = (sidx + 1 == NSTAGE) ? 0 : sidx + 1;
    }

    // epilogue: h = silu(g)*u -> fp16
    int gid = lane >> 2, t2 = (lane & 3) * 2;
    int colb = n0 + wn*32 + t2;
#pragma unroll
    for (int mt = 0; mt < 2; mt++) {
        int rbase = row0 + wm*32 + mt*16;
#pragma unroll
        for (int hfx = 0; hfx < 2; hfx++) {
            int r = rbase + gid + hfx*8;
            if (r < rowEnd) {
                size_t ro = (size_t)r * HPAD + colb;
#pragma unroll
                for (int nt = 0; nt < 4; nt++) {
                    float g0 = accg[mt][nt][hfx*2+0], g1 = accg[mt][nt][hfx*2+1];
                    float u0 = accu[mt][nt][hfx*2+0], u1 = accu[mt][nt][hfx*2+1];
                    float h0 = g0 / (1.f + expf(-g0)) * u0;
                    float h1 = g1 / (1.f + expf(-g1)) * u1;
                    *(uint32_t*)(H + ro + nt*8) = packh2(h0, h1);
                }
            }
        }
    }
}

// ---------------- down GEMM (CTA 256x128, 16 warps 4x4) ----------------------
// A: 256x32 fp16 @ st+0; Bh @ st+20480 (128x32); Bl @ st+30720
__global__ void __launch_bounds__(512, 1)
down_mma(const hf* __restrict__ A, int ldA,
         const hf* __restrict__ Bh, const hf* __restrict__ Bl,
         size_t bestride, float* __restrict__ Y, const float* __restrict__ scale,
         const int* __restrict__ offs, const int* __restrict__ cnts)
{
    extern __shared__ __align__(256) char smem[];
    int e = blockIdx.z;
    int off = offs[e], cnt = cnts[e];
    int row0 = off + blockIdx.y * 256, rowEnd = off + cnt;
    if (row0 >= rowEnd) return;
    int clampA = rowEnd - 1;
    int n0 = blockIdx.x * 128;
    const hf* bh_g = Bh + (size_t)e * bestride;
    const hf* bl_g = Bl + (size_t)e * bestride;

    uint32_t SB = smem_u32(smem);
    int tid = threadIdx.x, wid = tid >> 5, lane = tid & 31;
    int wm = wid >> 2, wn = wid & 3;

    float acc[4][4][4];
#pragma unroll
    for (int a = 0; a < 4; a++)
#pragma unroll
        for (int b = 0; b < 4; b++)
#pragma unroll
            for (int c = 0; c < 4; c++) acc[a][b][c] = 0.f;

    uint32_t aoff = (uint32_t)(wm*64 + (lane & 15)) * 80u + ((lane & 16) ? 16u : 0u);
    uint32_t bpo = (uint32_t)(wn*32 + (lane & 7)) * 80u + ((lane & 8) ? 16u : 0u)
                 + ((lane & 16) ? 640u : 0u);

    const int NCH = HPAD / 32;  // 88
#pragma unroll 1
    for (int i = 0; i < NSTAGE; i++) {
        uint32_t st = SB + (uint32_t)i * STAGE_B;
        int kc = i * 32;
        ld_tile(st +     0, A,    ldA,  row0, clampA,     kc, 256, tid);
        ld_tile(st + 20480, bh_g, HPAD, n0,   0x7fffffff, kc, 128, tid);
        ld_tile(st + 30720, bl_g, HPAD, n0,   0x7fffffff, kc, 128, tid);
        CP_COMMIT();
    }
    int sidx = 0;
#pragma unroll 1
    for (int i = 0; i < NCH; i++) {
        uint32_t st = SB + (uint32_t)sidx * STAGE_B;
        CP_WAIT2();
        __syncthreads();
#pragma unroll
        for (int ks = 0; ks < 2; ks++) {
            uint32_t kb = ks * 32;
            uint32_t af[4][4];
#pragma unroll
            for (int mt = 0; mt < 4; mt++)
                ldsm4(af[mt], st + aoff + mt*1280 + kb);
            uint32_t bH[4][2], bL[4][2];
            {
                uint32_t tmp[4];
                ldsm4(tmp, st + 20480 + bpo + kb);
                bH[0][0]=tmp[0]; bH[0][1]=tmp[1]; bH[1][0]=tmp[2]; bH[1][1]=tmp[3];
                ldsm4(tmp, st + 20480 + bpo + 1280 + kb);
                bH[2][0]=tmp[0]; bH[2][1]=tmp[1]; bH[3][0]=tmp[2]; bH[3][1]=tmp[3];
                ldsm4(tmp, st + 30720 + bpo + kb);
                bL[0][0]=tmp[0]; bL[0][1]=tmp[1]; bL[1][0]=tmp[2]; bL[1][1]=tmp[3];
                ldsm4(tmp, st + 30720 + bpo + 1280 + kb);
                bL[2][0]=tmp[0]; bL[2][1]=tmp[1]; bL[3][0]=tmp[2]; bL[3][1]=tmp[3];
            }
#pragma unroll
            for (int nt = 0; nt < 4; nt++)
#pragma unroll
                for (int mt = 0; mt < 4; mt++) {
                    mma16816(acc[mt][nt], af[mt], bH[nt]);
                    mma16816(acc[mt][nt], af[mt], bL[nt]);
                }
        }
        __syncthreads();
        if (i + NSTAGE < NCH) {
            int kc = (i + NSTAGE) * 32;
            ld_tile(st +     0, A,    ldA,  row0, clampA,     kc, 256, tid);
            ld_tile(st + 20480, bh_g, HPAD, n0,   0x7fffffff, kc, 128, tid);
            ld_tile(st + 30720, bl_g, HPAD, n0,   0x7fffffff, kc, 128, tid);
        }
        CP_COMMIT();
        sidx = (sidx + 1 == NSTAGE) ? 0 : sidx + 1;
    }

    int gid = lane >> 2, t2 = (lane & 3) * 2;
    int colb = n0 + wn*32 + t2;
#pragma unroll
    for (int mt = 0; mt < 4; mt++) {
        int rbase = row0 + wm*64 + mt*16;
#pragma unroll
        for (int hfx = 0; hfx < 2; hfx++) {
            int r = rbase + gid + hfx*8;
            if (r < rowEnd) {
                float sc = scale ? scale[r] : 1.f;
                float* yp = Y + (size_t)r * CDIM + colb;
#pragma unroll
                for (int nt = 0; nt < 4; nt++) {
                    float2 v;
                    v.x = acc[mt][nt][hfx*2+0] * sc;
                    v.y = acc[mt][nt][hfx*2+1] * sc;
                    *(float2*)(yp + nt*8) = v;
                }
            }
        }
    }
}

// ---------------- combine / aux ----------------------------------------------
__global__ void combine_kernel(float* __restrict__ out) {
    int t = blockIdx.x;
    int p0 = g_pos[t*2+0], p1 = g_pos[t*2+1];
    const float4* a = (const float4*)(g_yd + (size_t)p0 * CDIM);
    const float4* b = (const float4*)(g_yd + (size_t)p1 * CDIM);
    const float4* c = (const float4*)(g_ys + (size_t)t  * CDIM);
    float4* o = (float4*)(out + (size_t)t * CDIM);
    int i = threadIdx.x;
    float4 va = a[i], vb = b[i], vc = c[i];
    o[i] = make_float4(va.x+vb.x+vc.x, va.y+vb.y+vc.y,
                       va.z+vb.z+vc.z, va.w+vb.w+vc.w);
}

__global__ void aux_kernel(float* __restrict__ dst) {
    float a = 0.f;
    for (int e = 0; e < NEXP; e++) {
        float f = (float)g_cnt[e] / (float)(TK * TOPK);
        float p = g_psum[e] / (float)TK;
        a += f * p;
    }
    dst[0] = (float)NEXP * a;
}

// ---------------- launch -----------------------------------------------------
extern "C" void kernel_launch(void* const* d_in, const int* in_sizes, int n_in,
                              void* d_out, int out_size) {
    const float* x  = (const float*)d_in[0];
    const float* rw = (const float*)d_in[1];
    const float* wg = (const float*)d_in[2];
    const float* wu = (const float*)d_in[3];
    const float* wd = (const float*)d_in[4];
    const float* sg = (const float*)d_in[5];
    const float* su = (const float*)d_in[6];
    const float* sd = (const float*)d_in[7];
    float* out = (float*)d_out;

    cudaFuncSetAttribute(gateup_mma, cudaFuncAttributeMaxDynamicSharedMemorySize,
                         NSTAGE * STAGE_B);
    cudaFuncSetAttribute(down_mma, cudaFuncAttributeMaxDynamicSharedMemorySize,
                         NSTAGE * STAGE_B);

    hf *p_xg, *p_xs;
    hf *p_wgTh, *p_wgTl, *p_wuTh, *p_wuTl, *p_wdTh, *p_wdTl;
    hf *p_sgTh, *p_sgTl, *p_suTh, *p_suTl, *p_sdTh, *p_sdTl;
    hf *p_h, *p_hs;
    float *p_yd, *p_ys, *p_pw;
    int *p_off, *p_cnt, *p_soff, *p_scnt;
    cudaGetSymbolAddress((void**)&p_xg, g_xg);
    cudaGetSymbolAddress((void**)&p_xs, g_xs);
    cudaGetSymbolAddress((void**)&p_wgTh, g_wgTh);
    cudaGetSymbolAddress((void**)&p_wgTl, g_wgTl);
    cudaGetSymbolAddress((void**)&p_wuTh, g_wuTh);
    cudaGetSymbolAddress((void**)&p_wuTl, g_wuTl);
    cudaGetSymbolAddress((void**)&p_wdTh, g_wdTh);
    cudaGetSymbolAddress((void**)&p_wdTl, g_wdTl);
    cudaGetSymbolAddress((void**)&p_sgTh, g_sgTh);
    cudaGetSymbolAddress((void**)&p_sgTl, g_sgTl);
    cudaGetSymbolAddress((void**)&p_suTh, g_suTh);
    cudaGetSymbolAddress((void**)&p_suTl, g_suTl);
    cudaGetSymbolAddress((void**)&p_sdTh, g_sdTh);
    cudaGetSymbolAddress((void**)&p_sdTl, g_sdTl);
    cudaGetSymbolAddress((void**)&p_h, g_h);
    cudaGetSymbolAddress((void**)&p_hs, g_hs);
    cudaGetSymbolAddress((void**)&p_yd, g_yd);
    cudaGetSymbolAddress((void**)&p_ys, g_ys);
    cudaGetSymbolAddress((void**)&p_pw, g_pw);
    cudaGetSymbolAddress((void**)&p_off, g_off);
    cudaGetSymbolAddress((void**)&p_cnt, g_cnt);
    cudaGetSymbolAddress((void**)&p_soff, g_soff);
    cudaGetSymbolAddress((void**)&p_scnt, g_scnt);

    zero_kernel<<<1, 32>>>();
    router_kernel<<<TK/4, 128>>>(x, rw);
    offsets_kernel<<<1, 1>>>();
    scatter_kernel<<<16, 256>>>();

    gather_half<<<NPAIR, 256>>>(x);
    xhalf<<<TK, 256>>>(x);

    dim3 tb(32, 8);
    tsplit<<<dim3(HPAD/32, CDIM/32, NEXP), tb>>>(wg, CDIM, HDIM,
        (size_t)CDIM*HDIM, p_wgTh, p_wgTl, CDIM, (size_t)HPAD*CDIM);
    tsplit<<<dim3(HPAD/32, CDIM/32, NEXP), tb>>>(wu, CDIM, HDIM,
        (size_t)CDIM*HDIM, p_wuTh, p_wuTl, CDIM, (size_t)HPAD*CDIM);
    tsplit<<<dim3(CDIM/32, HPAD/32, NEXP), tb>>>(wd, HDIM, CDIM,
        (size_t)HDIM*CDIM, p_wdTh, p_wdTl, HPAD, (size_t)CDIM*HPAD);
    tsplit<<<dim3(HPAD/32, CDIM/32, 1), tb>>>(sg, CDIM, HDIM,
        0, p_sgTh, p_sgTl, CDIM, 0);
    tsplit<<<dim3(HPAD/32, CDIM/32, 1), tb>>>(su, CDIM, HDIM,
        0, p_suTh, p_suTl, CDIM, 0);
    tsplit<<<dim3(CDIM/32, HPAD/32, 1), tb>>>(sd, HDIM, CDIM,
        0, p_sdTh, p_sdTl, HPAD, 0);

    // expert gate/up + SwiGLU
    gateup_mma<<<dim3(HPAD/64, NPAIR/256, NEXP), 512, NSTAGE*STAGE_B>>>(
        p_xg, CDIM, p_wgTh, p_wgTl, p_wuTh, p_wuTl,
        (size_t)HPAD*CDIM, p_h, p_off, p_cnt);
    // shared gate/up
    gateup_mma<<<dim3(HPAD/64, TK/256, 1), 512, NSTAGE*STAGE_B>>>(
        p_xs, CDIM, p_sgTh, p_sgTl, p_suTh, p_suTl,
        0, p_hs, p_soff, p_scnt);

    // expert down (router-weight scaled)
    down_mma<<<dim3(CDIM/128, NPAIR/256, NEXP), 512, NSTAGE*STAGE_B>>>(
        p_h, HPAD, p_wdTh, p_wdTl, (size_t)CDIM*HPAD,
        p_yd, p_pw, p_off, p_cnt);
    // shared down
    down_mma<<<dim3(CDIM/128, TK/256, 1), 512, NSTAGE*STAGE_B>>>(
        p_hs, HPAD, p_sdTh, p_sdTl, 0,
        p_ys, nullptr, p_soff, p_scnt);

    combine_kernel<<<TK, 256>>>(out);

    if (out_size > TK * CDIM)
        aux_kernel<<<1, 1>>>(out + (size_t)TK * CDIM);
}

// round 8
// speedup vs baseline: 3.3704x; 1.1096x over previous
#include <cuda_runtime.h>
#include <cuda_fp16.h>
#include <math.h>
#include <stdint.h>

#define TK    4096
#define CDIM  1024
#define NEXP  8
#define TOPK  2
#define HDIM  2736
#define HPAD  2816
#define NPAIR (TK*TOPK)

typedef __half hf;

// ---------------- PTX helpers ------------------------------------------------
__device__ __forceinline__ uint32_t smem_u32(const void* p) {
    uint32_t a;
    asm("{ .reg .u64 t; cvta.to.shared.u64 t, %1; cvt.u32.u64 %0, t; }"
        : "=r"(a) : "l"(p));
    return a;
}
__device__ __forceinline__ void cpa16(uint32_t d, const void* s) {
    asm volatile("cp.async.cg.shared.global [%0], [%1], 16;" :: "r"(d), "l"(s));
}
#define CP_COMMIT() asm volatile("cp.async.commit_group;" ::: "memory")
#define CP_WAIT2()  asm volatile("cp.async.wait_group 2;" ::: "memory")

__device__ __forceinline__ void ldsm4(uint32_t* r, uint32_t a) {
    asm volatile("ldmatrix.sync.aligned.m8n8.x4.shared.b16 {%0,%1,%2,%3}, [%4];"
        : "=r"(r[0]), "=r"(r[1]), "=r"(r[2]), "=r"(r[3]) : "r"(a));
}
__device__ __forceinline__ void mma16816(float* d, const uint32_t* a, const uint32_t* b) {
    asm volatile("mma.sync.aligned.m16n8k16.row.col.f32.f16.f16.f32 "
        "{%0,%1,%2,%3}, {%4,%5,%6,%7}, {%8,%9}, {%0,%1,%2,%3};"
        : "+f"(d[0]), "+f"(d[1]), "+f"(d[2]), "+f"(d[3])
        : "r"(a[0]), "r"(a[1]), "r"(a[2]), "r"(a[3]), "r"(b[0]), "r"(b[1]));
}

// ---------------- scratch ----------------------------------------------------
__device__ int   g_cnt[NEXP];
__device__ int   g_off[NEXP];
__device__ int   g_cur[NEXP];
__device__ float g_psum[NEXP];
__device__ int   g_soff[1];
__device__ int   g_scnt[1];
__device__ int   g_top_i[TK*TOPK];
__device__ float g_top_w[TK*TOPK];
__device__ int   g_perm[NPAIR];
__device__ float g_pw[NPAIR];
__device__ int   g_pos[TK*TOPK];

__device__ __align__(256) hf g_xg[(size_t)NPAIR*CDIM];
__device__ __align__(256) hf g_xs[(size_t)TK*CDIM];
__device__ __align__(256) hf g_wgTh[(size_t)NEXP*HPAD*CDIM];
__device__ __align__(256) hf g_wgTl[(size_t)NEXP*HPAD*CDIM];
__device__ __align__(256) hf g_wuTh[(size_t)NEXP*HPAD*CDIM];
__device__ __align__(256) hf g_wuTl[(size_t)NEXP*HPAD*CDIM];
__device__ __align__(256) hf g_wdTh[(size_t)NEXP*CDIM*HPAD];
__device__ __align__(256) hf g_wdTl[(size_t)NEXP*CDIM*HPAD];
__device__ __align__(256) hf g_sgTh[(size_t)HPAD*CDIM];
__device__ __align__(256) hf g_sgTl[(size_t)HPAD*CDIM];
__device__ __align__(256) hf g_suTh[(size_t)HPAD*CDIM];
__device__ __align__(256) hf g_suTl[(size_t)HPAD*CDIM];
__device__ __align__(256) hf g_sdTh[(size_t)CDIM*HPAD];
__device__ __align__(256) hf g_sdTl[(size_t)CDIM*HPAD];
__device__ __align__(256) hf g_h [(size_t)NPAIR*HPAD];
__device__ __align__(256) hf g_hs[(size_t)TK*HPAD];
__device__ __align__(256) float g_yd[(size_t)NPAIR*CDIM];
__device__ __align__(256) float g_ys[(size_t)TK*CDIM];

// ---------------- small kernels ----------------------------------------------
__global__ void zero_kernel() {
    int t = threadIdx.x;
    if (t < NEXP) { g_cnt[t] = 0; g_psum[t] = 0.f; }
}

__global__ void router_kernel(const float* __restrict__ x,
                              const float* __restrict__ rw) {
    int warp = threadIdx.x >> 5, lane = threadIdx.x & 31;
    int t = blockIdx.x * (blockDim.x >> 5) + warp;
    if (t >= TK) return;
    const float* xr = x + (size_t)t * CDIM;
    float acc[NEXP];
#pragma unroll
    for (int e = 0; e < NEXP; e++) acc[e] = 0.f;
    for (int c = lane; c < CDIM; c += 32) {
        float xv = xr[c];
        const float4* rp = (const float4*)(rw + (size_t)c * NEXP);
        float4 r0 = rp[0], r1 = rp[1];
        acc[0] += xv*r0.x; acc[1] += xv*r0.y; acc[2] += xv*r0.z; acc[3] += xv*r0.w;
        acc[4] += xv*r1.x; acc[5] += xv*r1.y; acc[6] += xv*r1.z; acc[7] += xv*r1.w;
    }
#pragma unroll
    for (int e = 0; e < NEXP; e++)
#pragma unroll
        for (int s = 16; s; s >>= 1)
            acc[e] += __shfl_xor_sync(0xffffffffu, acc[e], s);
    if (lane == 0) {
        int i0 = 0; float v0 = acc[0];
#pragma unroll
        for (int e = 1; e < NEXP; e++) if (acc[e] > v0) { v0 = acc[e]; i0 = e; }
        int i1 = -1; float v1 = -INFINITY;
#pragma unroll
        for (int e = 0; e < NEXP; e++)
            if (e != i0 && acc[e] > v1) { v1 = acc[e]; i1 = e; }
        float w0 = 1.f / (1.f + expf(v1 - v0));
        g_top_i[t*2+0] = i0; g_top_i[t*2+1] = i1;
        g_top_w[t*2+0] = w0; g_top_w[t*2+1] = 1.f - w0;
        atomicAdd(&g_cnt[i0], 1); atomicAdd(&g_cnt[i1], 1);
        float s = 0.f, pe[NEXP];
#pragma unroll
        for (int e = 0; e < NEXP; e++) { pe[e] = expf(acc[e] - v0); s += pe[e]; }
        float inv = 1.f / s;
#pragma unroll
        for (int e = 0; e < NEXP; e++) atomicAdd(&g_psum[e], pe[e] * inv);
    }
}

__global__ void offsets_kernel() {
    int o = 0;
    for (int e = 0; e < NEXP; e++) { g_off[e] = o; g_cur[e] = o; o += g_cnt[e]; }
    g_soff[0] = 0; g_scnt[0] = TK;
}

__global__ void scatter_kernel() {
    int t = blockIdx.x * blockDim.x + threadIdx.x;
    if (t >= TK) return;
#pragma unroll
    for (int k = 0; k < TOPK; k++) {
        int e = g_top_i[t*2+k];
        int pos = atomicAdd(&g_cur[e], 1);
        g_perm[pos] = t;
        g_pw[pos]   = g_top_w[t*2+k];
        g_pos[t*2+k] = pos;
    }
}

__device__ __forceinline__ uint32_t packh2(float a, float b) {
    __half2 t = __floats2half2_rn(a, b);
    return *reinterpret_cast<uint32_t*>(&t);
}

__global__ void gather_half(const float* __restrict__ x) {
    int p = blockIdx.x;
    int src = g_perm[p];
    float4 v = ((const float4*)(x + (size_t)src * CDIM))[threadIdx.x];
    uint2 h;
    h.x = packh2(v.x, v.y); h.y = packh2(v.z, v.w);
    ((uint2*)(g_xg + (size_t)p * CDIM))[threadIdx.x] = h;
}

__global__ void xhalf(const float* __restrict__ x) {
    int t = blockIdx.x;
    float4 v = ((const float4*)(x + (size_t)t * CDIM))[threadIdx.x];
    uint2 h;
    h.x = packh2(v.x, v.y); h.y = packh2(v.z, v.w);
    ((uint2*)(g_xs + (size_t)t * CDIM))[threadIdx.x] = h;
}

// transpose+split: in [K,N] fp32 -> out [Npad rows][Kpad cols] fp16 hi/lo
__global__ void tsplit(const float* __restrict__ in, int K, int N, size_t in_bs,
                       hf* __restrict__ oh, hf* __restrict__ ol,
                       int Kpad, size_t out_bs) {
    __shared__ float t[32][33];
    int b = blockIdx.z;
    in += (size_t)b * in_bs; oh += (size_t)b * out_bs; ol += (size_t)b * out_bs;
    int nb = blockIdx.x * 32, kb = blockIdx.y * 32;
    int tx = threadIdx.x, ty = threadIdx.y;
#pragma unroll
    for (int i = 0; i < 4; i++) {
        int k = kb + ty + i*8, n = nb + tx;
        t[ty + i*8][tx] = (k < K && n < N) ? in[(size_t)k * N + n] : 0.f;
    }
    __syncthreads();
#pragma unroll
    for (int i = 0; i < 4; i++) {
        int n = nb + ty + i*8, k = kb + tx;
        float v = t[tx][ty + i*8];
        hf h = __float2half_rn(v);
        oh[(size_t)n * Kpad + k] = h;
        ol[(size_t)n * Kpad + k] = __float2half_rn(v - __half2float(h));
    }
}

// ---------------- tile loader: rows x 32 halfs, 80B row stride ---------------
__device__ __forceinline__ void ld_tile(uint32_t dst, const hf* __restrict__ g,
                                        int ldg, int rbase, int clampv, int kc,
                                        int rows, int tid) {
    int chunks = rows * 4;
    for (int c = tid; c < chunks; c += 512) {
        int r = c >> 2, cb = (c & 3) << 4;
        int row = rbase + r; if (row > clampv) row = clampv;
        cpa16(dst + (uint32_t)r * 80u + cb,
              (const char*)(g + (size_t)row * ldg + kc) + cb);
    }
}

#define STAGE_B 40960u
#define NSTAGE  4

// ---------------- gate/up GEMM + SwiGLU (CTA 256x64, 16 warps 8x2) -----------
__global__ void __launch_bounds__(512, 1)
gateup_mma(const hf* __restrict__ A, int ldA,
           const hf* __restrict__ BGh, const hf* __restrict__ BGl,
           const hf* __restrict__ BUh, const hf* __restrict__ BUl,
           size_t bestride, hf* __restrict__ H,
           const int* __restrict__ offs, const int* __restrict__ cnts)
{
    extern __shared__ __align__(256) char smem[];
    int e = blockIdx.z;
    int off = offs[e], cnt = cnts[e];
    int row0 = off + blockIdx.y * 256, rowEnd = off + cnt;
    if (row0 >= rowEnd) return;
    int clampA = rowEnd - 1;
    int n0 = blockIdx.x * 64;
    const hf* bgh = BGh + (size_t)e * bestride;
    const hf* bgl = BGl + (size_t)e * bestride;
    const hf* buh = BUh + (size_t)e * bestride;
    const hf* bul = BUl + (size_t)e * bestride;

    uint32_t SB = smem_u32(smem);
    int tid = threadIdx.x, wid = tid >> 5, lane = tid & 31;
    int wm = wid >> 1, wn = wid & 1;

    float accg[2][4][4], accu[2][4][4];
#pragma unroll
    for (int a = 0; a < 2; a++)
#pragma unroll
        for (int b = 0; b < 4; b++)
#pragma unroll
            for (int c = 0; c < 4; c++) { accg[a][b][c] = 0.f; accu[a][b][c] = 0.f; }

    uint32_t aoff = (uint32_t)(wm*32 + (lane & 15)) * 80u + ((lane & 16) ? 16u : 0u);
    uint32_t bpo = (uint32_t)(wn*32 + (lane & 7)) * 80u + ((lane & 8) ? 16u : 0u)
                 + ((lane & 16) ? 640u : 0u);

    const int NCH = CDIM / 32;  // 32
    // prologue: chunks 0..2 into stages 0..2
#pragma unroll 1
    for (int i = 0; i < NSTAGE - 1; i++) {
        uint32_t st = SB + (uint32_t)i * STAGE_B;
        int kc = i * 32;
        ld_tile(st +     0, A,   ldA,  row0, clampA,     kc, 256, tid);
        ld_tile(st + 20480, bgh, CDIM, n0,   0x7fffffff, kc, 64, tid);
        ld_tile(st + 25600, bgl, CDIM, n0,   0x7fffffff, kc, 64, tid);
        ld_tile(st + 30720, buh, CDIM, n0,   0x7fffffff, kc, 64, tid);
        ld_tile(st + 35840, bul, CDIM, n0,   0x7fffffff, kc, 64, tid);
        CP_COMMIT();
    }
#pragma unroll 1
    for (int i = 0; i < NCH; i++) {
        uint32_t st = SB + (uint32_t)(i & 3) * STAGE_B;
        CP_WAIT2();
        __syncthreads();
        // issue chunk i+3 into stage (i+3)&3 (= (i-1)&3, drained by the sync)
        int nc = i + NSTAGE - 1;
        if (nc < NCH) {
            uint32_t wst = SB + (uint32_t)(nc & 3) * STAGE_B;
            int kc = nc * 32;
            ld_tile(wst +     0, A,   ldA,  row0, clampA,     kc, 256, tid);
            ld_tile(wst + 20480, bgh, CDIM, n0,   0x7fffffff, kc, 64, tid);
            ld_tile(wst + 25600, bgl, CDIM, n0,   0x7fffffff, kc, 64, tid);
            ld_tile(wst + 30720, buh, CDIM, n0,   0x7fffffff, kc, 64, tid);
            ld_tile(wst + 35840, bul, CDIM, n0,   0x7fffffff, kc, 64, tid);
        }
        CP_COMMIT();
#pragma unroll
        for (int ks = 0; ks < 2; ks++) {
            uint32_t kb = ks * 32;
            uint32_t af[2][4];
            ldsm4(af[0], st + aoff + kb);
            ldsm4(af[1], st + aoff + 1280 + kb);
            uint32_t bgH[4][2], bgL[4][2], buH[4][2], buL[4][2];
            {
                uint32_t tmp[4];
                ldsm4(tmp, st + 20480 + bpo + kb);
                bgH[0][0]=tmp[0]; bgH[0][1]=tmp[1]; bgH[1][0]=tmp[2]; bgH[1][1]=tmp[3];
                ldsm4(tmp, st + 20480 + bpo + 1280 + kb);
                bgH[2][0]=tmp[0]; bgH[2][1]=tmp[1]; bgH[3][0]=tmp[2]; bgH[3][1]=tmp[3];
                ldsm4(tmp, st + 25600 + bpo + kb);
                bgL[0][0]=tmp[0]; bgL[0][1]=tmp[1]; bgL[1][0]=tmp[2]; bgL[1][1]=tmp[3];
                ldsm4(tmp, st + 25600 + bpo + 1280 + kb);
                bgL[2][0]=tmp[0]; bgL[2][1]=tmp[1]; bgL[3][0]=tmp[2]; bgL[3][1]=tmp[3];
                ldsm4(tmp, st + 30720 + bpo + kb);
                buH[0][0]=tmp[0]; buH[0][1]=tmp[1]; buH[1][0]=tmp[2]; buH[1][1]=tmp[3];
                ldsm4(tmp, st + 30720 + bpo + 1280 + kb);
                buH[2][0]=tmp[0]; buH[2][1]=tmp[1]; buH[3][0]=tmp[2]; buH[3][1]=tmp[3];
                ldsm4(tmp, st + 35840 + bpo + kb);
                buL[0][0]=tmp[0]; buL[0][1]=tmp[1]; buL[1][0]=tmp[2]; buL[1][1]=tmp[3];
                ldsm4(tmp, st + 35840 + bpo + 1280 + kb);
                buL[2][0]=tmp[0]; buL[2][1]=tmp[1]; buL[3][0]=tmp[2]; buL[3][1]=tmp[3];
            }
#pragma unroll
            for (int mt = 0; mt < 2; mt++)
#pragma unroll
                for (int nt = 0; nt < 4; nt++) {
                    mma16816(accg[mt][nt], af[mt], bgH[nt]);
                    mma16816(accg[mt][nt], af[mt], bgL[nt]);
                    mma16816(accu[mt][nt], af[mt], buH[nt]);
                    mma16816(accu[mt][nt], af[mt], buL[nt]);
                }
        }
    }

    // epilogue: h = silu(g)*u -> fp16
    int gid = lane >> 2, t2 = (lane & 3) * 2;
    int colb = n0 + wn*32 + t2;
#pragma unroll
    for (int mt = 0; mt < 2; mt++) {
        int rbase = row0 + wm*32 + mt*16;
#pragma unroll
        for (int hfx = 0; hfx < 2; hfx++) {
            int r = rbase + gid + hfx*8;
            if (r < rowEnd) {
                size_t ro = (size_t)r * HPAD + colb;
#pragma unroll
                for (int nt = 0; nt < 4; nt++) {
                    float g0 = accg[mt][nt][hfx*2+0], g1 = accg[mt][nt][hfx*2+1];
                    float u0 = accu[mt][nt][hfx*2+0], u1 = accu[mt][nt][hfx*2+1];
                    float h0 = g0 / (1.f + expf(-g0)) * u0;
                    float h1 = g1 / (1.f + expf(-g1)) * u1;
                    *(uint32_t*)(H + ro + nt*8) = packh2(h0, h1);
                }
            }
        }
    }
}

// ---------------- down GEMM (CTA 256x128, 16 warps 4x4) ----------------------
__global__ void __launch_bounds__(512, 1)
down_mma(const hf* __restrict__ A, int ldA,
         const hf* __restrict__ Bh, const hf* __restrict__ Bl,
         size_t bestride, float* __restrict__ Y, const float* __restrict__ scale,
         const int* __restrict__ offs, const int* __restrict__ cnts)
{
    extern __shared__ __align__(256) char smem[];
    int e = blockIdx.z;
    int off = offs[e], cnt = cnts[e];
    int row0 = off + blockIdx.y * 256, rowEnd = off + cnt;
    if (row0 >= rowEnd) return;
    int clampA = rowEnd - 1;
    int n0 = blockIdx.x * 128;
    const hf* bh_g = Bh + (size_t)e * bestride;
    const hf* bl_g = Bl + (size_t)e * bestride;

    uint32_t SB = smem_u32(smem);
    int tid = threadIdx.x, wid = tid >> 5, lane = tid & 31;
    int wm = wid >> 2, wn = wid & 3;

    float acc[4][4][4];
#pragma unroll
    for (int a = 0; a < 4; a++)
#pragma unroll
        for (int b = 0; b < 4; b++)
#pragma unroll
            for (int c = 0; c < 4; c++) acc[a][b][c] = 0.f;

    uint32_t aoff = (uint32_t)(wm*64 + (lane & 15)) * 80u + ((lane & 16) ? 16u : 0u);
    uint32_t bpo = (uint32_t)(wn*32 + (lane & 7)) * 80u + ((lane & 8) ? 16u : 0u)
                 + ((lane & 16) ? 640u : 0u);

    const int NCH = HPAD / 32;  // 88
#pragma unroll 1
    for (int i = 0; i < NSTAGE - 1; i++) {
        uint32_t st = SB + (uint32_t)i * STAGE_B;
        int kc = i * 32;
        ld_tile(st +     0, A,    ldA,  row0, clampA,     kc, 256, tid);
        ld_tile(st + 20480, bh_g, HPAD, n0,   0x7fffffff, kc, 128, tid);
        ld_tile(st + 30720, bl_g, HPAD, n0,   0x7fffffff, kc, 128, tid);
        CP_COMMIT();
    }
#pragma unroll 1
    for (int i = 0; i < NCH; i++) {
        uint32_t st = SB + (uint32_t)(i & 3) * STAGE_B;
        CP_WAIT2();
        __syncthreads();
        int nc = i + NSTAGE - 1;
        if (nc < NCH) {
            uint32_t wst = SB + (uint32_t)(nc & 3) * STAGE_B;
            int kc = nc * 32;
            ld_tile(wst +     0, A,    ldA,  row0, clampA,     kc, 256, tid);
            ld_tile(wst + 20480, bh_g, HPAD, n0,   0x7fffffff, kc, 128, tid);
            ld_tile(wst + 30720, bl_g, HPAD, n0,   0x7fffffff, kc, 128, tid);
        }
        CP_COMMIT();
#pragma unroll
        for (int ks = 0; ks < 2; ks++) {
            uint32_t kb = ks * 32;
            uint32_t af[4][4];
#pragma unroll
            for (int mt = 0; mt < 4; mt++)
                ldsm4(af[mt], st + aoff + mt*1280 + kb);
            uint32_t bH[4][2], bL[4][2];
            {
                uint32_t tmp[4];
                ldsm4(tmp, st + 20480 + bpo + kb);
                bH[0][0]=tmp[0]; bH[0][1]=tmp[1]; bH[1][0]=tmp[2]; bH[1][1]=tmp[3];
                ldsm4(tmp, st + 20480 + bpo + 1280 + kb);
                bH[2][0]=tmp[0]; bH[2][1]=tmp[1]; bH[3][0]=tmp[2]; bH[3][1]=tmp[3];
                ldsm4(tmp, st + 30720 + bpo + kb);
                bL[0][0]=tmp[0]; bL[0][1]=tmp[1]; bL[1][0]=tmp[2]; bL[1][1]=tmp[3];
                ldsm4(tmp, st + 30720 + bpo + 1280 + kb);
                bL[2][0]=tmp[0]; bL[2][1]=tmp[1]; bL[3][0]=tmp[2]; bL[3][1]=tmp[3];
            }
#pragma unroll
            for (int nt = 0; nt < 4; nt++)
#pragma unroll
                for (int mt = 0; mt < 4; mt++) {
                    mma16816(acc[mt][nt], af[mt], bH[nt]);
                    mma16816(acc[mt][nt], af[mt], bL[nt]);
                }
        }
    }

    int gid = lane >> 2, t2 = (lane & 3) * 2;
    int colb = n0 + wn*32 + t2;
#pragma unroll
    for (int mt = 0; mt < 4; mt++) {
        int rbase = row0 + wm*64 + mt*16;
#pragma unroll
        for (int hfx = 0; hfx < 2; hfx++) {
            int r = rbase + gid + hfx*8;
            if (r < rowEnd) {
                float sc = scale ? scale[r] : 1.f;
                float* yp = Y + (size_t)r * CDIM + colb;
#pragma unroll
                for (int nt = 0; nt < 4; nt++) {
                    float2 v;
                    v.x = acc[mt][nt][hfx*2+0] * sc;
                    v.y = acc[mt][nt][hfx*2+1] * sc;
                    *(float2*)(yp + nt*8) = v;
                }
            }
        }
    }
}

// ---------------- combine / aux ----------------------------------------------
__global__ void combine_kernel(float* __restrict__ out) {
    int t = blockIdx.x;
    int p0 = g_pos[t*2+0], p1 = g_pos[t*2+1];
    const float4* a = (const float4*)(g_yd + (size_t)p0 * CDIM);
    const float4* b = (const float4*)(g_yd + (size_t)p1 * CDIM);
    const float4* c = (const float4*)(g_ys + (size_t)t  * CDIM);
    float4* o = (float4*)(out + (size_t)t * CDIM);
    int i = threadIdx.x;
    float4 va = a[i], vb = b[i], vc = c[i];
    o[i] = make_float4(va.x+vb.x+vc.x, va.y+vb.y+vc.y,
                       va.z+vb.z+vc.z, va.w+vb.w+vc.w);
}

__global__ void aux_kernel(float* __restrict__ dst) {
    float a = 0.f;
    for (int e = 0; e < NEXP; e++) {
        float f = (float)g_cnt[e] / (float)(TK * TOPK);
        float p = g_psum[e] / (float)TK;
        a += f * p;
    }
    dst[0] = (float)NEXP * a;
}

// ---------------- launch -----------------------------------------------------
extern "C" void kernel_launch(void* const* d_in, const int* in_sizes, int n_in,
                              void* d_out, int out_size) {
    const float* x  = (const float*)d_in[0];
    const float* rw = (const float*)d_in[1];
    const float* wg = (const float*)d_in[2];
    const float* wu = (const float*)d_in[3];
    const float* wd = (const float*)d_in[4];
    const float* sg = (const float*)d_in[5];
    const float* su = (const float*)d_in[6];
    const float* sd = (const float*)d_in[7];
    float* out = (float*)d_out;

    cudaFuncSetAttribute(gateup_mma, cudaFuncAttributeMaxDynamicSharedMemorySize,
                         NSTAGE * STAGE_B);
    cudaFuncSetAttribute(down_mma, cudaFuncAttributeMaxDynamicSharedMemorySize,
                         NSTAGE * STAGE_B);

    hf *p_xg, *p_xs;
    hf *p_wgTh, *p_wgTl, *p_wuTh, *p_wuTl, *p_wdTh, *p_wdTl;
    hf *p_sgTh, *p_sgTl, *p_suTh, *p_suTl, *p_sdTh, *p_sdTl;
    hf *p_h, *p_hs;
    float *p_yd, *p_ys, *p_pw;
    int *p_off, *p_cnt, *p_soff, *p_scnt;
    cudaGetSymbolAddress((void**)&p_xg, g_xg);
    cudaGetSymbolAddress((void**)&p_xs, g_xs);
    cudaGetSymbolAddress((void**)&p_wgTh, g_wgTh);
    cudaGetSymbolAddress((void**)&p_wgTl, g_wgTl);
    cudaGetSymbolAddress((void**)&p_wuTh, g_wuTh);
    cudaGetSymbolAddress((void**)&p_wuTl, g_wuTl);
    cudaGetSymbolAddress((void**)&p_wdTh, g_wdTh);
    cudaGetSymbolAddress((void**)&p_wdTl, g_wdTl);
    cudaGetSymbolAddress((void**)&p_sgTh, g_sgTh);
    cudaGetSymbolAddress((void**)&p_sgTl, g_sgTl);
    cudaGetSymbolAddress((void**)&p_suTh, g_suTh);
    cudaGetSymbolAddress((void**)&p_suTl, g_suTl);
    cudaGetSymbolAddress((void**)&p_sdTh, g_sdTh);
    cudaGetSymbolAddress((void**)&p_sdTl, g_sdTl);
    cudaGetSymbolAddress((void**)&p_h, g_h);
    cudaGetSymbolAddress((void**)&p_hs, g_hs);
    cudaGetSymbolAddress((void**)&p_yd, g_yd);
    cudaGetSymbolAddress((void**)&p_ys, g_ys);
    cudaGetSymbolAddress((void**)&p_pw, g_pw);
    cudaGetSymbolAddress((void**)&p_off, g_off);
    cudaGetSymbolAddress((void**)&p_cnt, g_cnt);
    cudaGetSymbolAddress((void**)&p_soff, g_soff);
    cudaGetSymbolAddress((void**)&p_scnt, g_scnt);

    zero_kernel<<<1, 32>>>();
    router_kernel<<<TK/4, 128>>>(x, rw);
    offsets_kernel<<<1, 1>>>();
    scatter_kernel<<<16, 256>>>();

    gather_half<<<NPAIR, 256>>>(x);
    xhalf<<<TK, 256>>>(x);

    dim3 tb(32, 8);
    tsplit<<<dim3(HPAD/32, CDIM/32, NEXP), tb>>>(wg, CDIM, HDIM,
        (size_t)CDIM*HDIM, p_wgTh, p_wgTl, CDIM, (size_t)HPAD*CDIM);
    tsplit<<<dim3(HPAD/32, CDIM/32, NEXP), tb>>>(wu, CDIM, HDIM,
        (size_t)CDIM*HDIM, p_wuTh, p_wuTl, CDIM, (size_t)HPAD*CDIM);
    tsplit<<<dim3(CDIM/32, HPAD/32, NEXP), tb>>>(wd, HDIM, CDIM,
        (size_t)HDIM*CDIM, p_wdTh, p_wdTl, HPAD, (size_t)CDIM*HPAD);
    tsplit<<<dim3(HPAD/32, CDIM/32, 1), tb>>>(sg, CDIM, HDIM,
        0, p_sgTh, p_sgTl, CDIM, 0);
    tsplit<<<dim3(HPAD/32, CDIM/32, 1), tb>>>(su, CDIM, HDIM,
        0, p_suTh, p_suTl, CDIM, 0);
    tsplit<<<dim3(CDIM/32, HPAD/32, 1), tb>>>(sd, HDIM, CDIM,
        0, p_sdTh, p_sdTl, HPAD, 0);

    // expert gate/up + SwiGLU
    gateup_mma<<<dim3(HPAD/64, NPAIR/256, NEXP), 512, NSTAGE*STAGE_B>>>(
        p_xg, CDIM, p_wgTh, p_wgTl, p_wuTh, p_wuTl,
        (size_t)HPAD*CDIM, p_h, p_off, p_cnt);
    // shared gate/up
    gateup_mma<<<dim3(HPAD/64, TK/256, 1), 512, NSTAGE*STAGE_B>>>(
        p_xs, CDIM, p_sgTh, p_sgTl, p_suTh, p_suTl,
        0, p_hs, p_soff, p_scnt);

    // expert down (router-weight scaled)
    down_mma<<<dim3(CDIM/128, NPAIR/256, NEXP), 512, NSTAGE*STAGE_B>>>(
        p_h, HPAD, p_wdTh, p_wdTl, (size_t)CDIM*HPAD,
        p_yd, p_pw, p_off, p_cnt);
    // shared down
    down_mma<<<dim3(CDIM/128, TK/256, 1), 512, NSTAGE*STAGE_B>>>(
        p_hs, HPAD, p_sdTh, p_sdTl, 0,
        p_ys, nullptr, p_soff, p_scnt);

    combine_kernel<<<TK, 256>>>(out);

    if (out_size > TK * CDIM)
        aux_kernel<<<1, 1>>>(out + (size_t)TK * CDIM);
}

// round 9
// speedup vs baseline: 4.6315x; 1.3742x over previous
#include <cuda_runtime.h>
#include <cuda_fp16.h>
#include <math.h>
#include <stdint.h>

#define TK    4096
#define CDIM  1024
#define NEXP  8
#define TOPK  2
#define HDIM  2736
#define HPAD  2816
#define NPAIR (TK*TOPK)

typedef __half hf;

// ---------------- PTX helpers ------------------------------------------------
__device__ __forceinline__ uint32_t smem_u32(const void* p) {
    uint32_t a;
    asm("{ .reg .u64 t; cvta.to.shared.u64 t, %1; cvt.u32.u64 %0, t; }"
        : "=r"(a) : "l"(p));
    return a;
}
__device__ __forceinline__ void cpa16(uint32_t d, const void* s) {
    asm volatile("cp.async.cg.shared.global [%0], [%1], 16;" :: "r"(d), "l"(s));
}
#define CP_COMMIT() asm volatile("cp.async.commit_group;" ::: "memory")
#define CP_WAIT2()  asm volatile("cp.async.wait_group 2;" ::: "memory")

__device__ __forceinline__ void ldsm4(uint32_t* r, uint32_t a) {
    asm volatile("ldmatrix.sync.aligned.m8n8.x4.shared.b16 {%0,%1,%2,%3}, [%4];"
        : "=r"(r[0]), "=r"(r[1]), "=r"(r[2]), "=r"(r[3]) : "r"(a));
}
__device__ __forceinline__ void mma16816(float* d, const uint32_t* a, const uint32_t* b) {
    asm volatile("mma.sync.aligned.m16n8k16.row.col.f32.f16.f16.f32 "
        "{%0,%1,%2,%3}, {%4,%5,%6,%7}, {%8,%9}, {%0,%1,%2,%3};"
        : "+f"(d[0]), "+f"(d[1]), "+f"(d[2]), "+f"(d[3])
        : "r"(a[0]), "r"(a[1]), "r"(a[2]), "r"(a[3]), "r"(b[0]), "r"(b[1]));
}

// ---------------- scratch ----------------------------------------------------
__device__ int   g_cnt[NEXP];
__device__ int   g_off[NEXP];
__device__ int   g_cur[NEXP];
__device__ float g_psum[NEXP];
__device__ int   g_soff[1];
__device__ int   g_scnt[1];
__device__ int   g_top_i[TK*TOPK];
__device__ float g_top_w[TK*TOPK];
__device__ int   g_perm[NPAIR];
__device__ float g_pw[NPAIR];
__device__ int   g_pos[TK*TOPK];

__device__ __align__(256) hf g_xg[(size_t)NPAIR*CDIM];
__device__ __align__(256) hf g_xs[(size_t)TK*CDIM];
__device__ __align__(256) hf g_wgT[(size_t)NEXP*HPAD*CDIM];
__device__ __align__(256) hf g_wuT[(size_t)NEXP*HPAD*CDIM];
__device__ __align__(256) hf g_wdT[(size_t)NEXP*CDIM*HPAD];
__device__ __align__(256) hf g_sgT[(size_t)HPAD*CDIM];
__device__ __align__(256) hf g_suT[(size_t)HPAD*CDIM];
__device__ __align__(256) hf g_sdT[(size_t)CDIM*HPAD];
__device__ __align__(256) hf g_h [(size_t)NPAIR*HPAD];
__device__ __align__(256) hf g_hs[(size_t)TK*HPAD];
__device__ __align__(256) float g_yd[(size_t)NPAIR*CDIM];
__device__ __align__(256) float g_ys[(size_t)TK*CDIM];

// ---------------- small kernels ----------------------------------------------
__global__ void zero_kernel() {
    int t = threadIdx.x;
    if (t < NEXP) { g_cnt[t] = 0; g_psum[t] = 0.f; }
}

__global__ void router_kernel(const float* __restrict__ x,
                              const float* __restrict__ rw) {
    int warp = threadIdx.x >> 5, lane = threadIdx.x & 31;
    int t = blockIdx.x * (blockDim.x >> 5) + warp;
    if (t >= TK) return;
    const float* xr = x + (size_t)t * CDIM;
    float acc[NEXP];
#pragma unroll
    for (int e = 0; e < NEXP; e++) acc[e] = 0.f;
    for (int c = lane; c < CDIM; c += 32) {
        float xv = xr[c];
        const float4* rp = (const float4*)(rw + (size_t)c * NEXP);
        float4 r0 = rp[0], r1 = rp[1];
        acc[0] += xv*r0.x; acc[1] += xv*r0.y; acc[2] += xv*r0.z; acc[3] += xv*r0.w;
        acc[4] += xv*r1.x; acc[5] += xv*r1.y; acc[6] += xv*r1.z; acc[7] += xv*r1.w;
    }
#pragma unroll
    for (int e = 0; e < NEXP; e++)
#pragma unroll
        for (int s = 16; s; s >>= 1)
            acc[e] += __shfl_xor_sync(0xffffffffu, acc[e], s);
    if (lane == 0) {
        int i0 = 0; float v0 = acc[0];
#pragma unroll
        for (int e = 1; e < NEXP; e++) if (acc[e] > v0) { v0 = acc[e]; i0 = e; }
        int i1 = -1; float v1 = -INFINITY;
#pragma unroll
        for (int e = 0; e < NEXP; e++)
            if (e != i0 && acc[e] > v1) { v1 = acc[e]; i1 = e; }
        float w0 = 1.f / (1.f + expf(v1 - v0));
        g_top_i[t*2+0] = i0; g_top_i[t*2+1] = i1;
        g_top_w[t*2+0] = w0; g_top_w[t*2+1] = 1.f - w0;
        atomicAdd(&g_cnt[i0], 1); atomicAdd(&g_cnt[i1], 1);
        float s = 0.f, pe[NEXP];
#pragma unroll
        for (int e = 0; e < NEXP; e++) { pe[e] = expf(acc[e] - v0); s += pe[e]; }
        float inv = 1.f / s;
#pragma unroll
        for (int e = 0; e < NEXP; e++) atomicAdd(&g_psum[e], pe[e] * inv);
    }
}

__global__ void offsets_kernel() {
    int o = 0;
    for (int e = 0; e < NEXP; e++) { g_off[e] = o; g_cur[e] = o; o += g_cnt[e]; }
    g_soff[0] = 0; g_scnt[0] = TK;
}

__global__ void scatter_kernel() {
    int t = blockIdx.x * blockDim.x + threadIdx.x;
    if (t >= TK) return;
#pragma unroll
    for (int k = 0; k < TOPK; k++) {
        int e = g_top_i[t*2+k];
        int pos = atomicAdd(&g_cur[e], 1);
        g_perm[pos] = t;
        g_pw[pos]   = g_top_w[t*2+k];
        g_pos[t*2+k] = pos;
    }
}

__device__ __forceinline__ uint32_t packh2(float a, float b) {
    __half2 t = __floats2half2_rn(a, b);
    return *reinterpret_cast<uint32_t*>(&t);
}

__global__ void gather_half(const float* __restrict__ x) {
    int p = blockIdx.x;
    int src = g_perm[p];
    float4 v = ((const float4*)(x + (size_t)src * CDIM))[threadIdx.x];
    uint2 h;
    h.x = packh2(v.x, v.y); h.y = packh2(v.z, v.w);
    ((uint2*)(g_xg + (size_t)p * CDIM))[threadIdx.x] = h;
}

__global__ void xhalf(const float* __restrict__ x) {
    int t = blockIdx.x;
    float4 v = ((const float4*)(x + (size_t)t * CDIM))[threadIdx.x];
    uint2 h;
    h.x = packh2(v.x, v.y); h.y = packh2(v.z, v.w);
    ((uint2*)(g_xs + (size_t)t * CDIM))[threadIdx.x] = h;
}

// transpose+convert: in [K,N] fp32 -> out [Npad rows][Kpad cols] fp16
__global__ void thalf(const float* __restrict__ in, int K, int N, size_t in_bs,
                      hf* __restrict__ oh, int Kpad, size_t out_bs) {
    __shared__ float t[32][33];
    int b = blockIdx.z;
    in += (size_t)b * in_bs; oh += (size_t)b * out_bs;
    int nb = blockIdx.x * 32, kb = blockIdx.y * 32;
    int tx = threadIdx.x, ty = threadIdx.y;
#pragma unroll
    for (int i = 0; i < 4; i++) {
        int k = kb + ty + i*8, n = nb + tx;
        t[ty + i*8][tx] = (k < K && n < N) ? in[(size_t)k * N + n] : 0.f;
    }
    __syncthreads();
#pragma unroll
    for (int i = 0; i < 4; i++) {
        int n = nb + ty + i*8, k = kb + tx;
        oh[(size_t)n * Kpad + k] = __float2half_rn(t[tx][ty + i*8]);
    }
}

// ---------------- tile loader: rows x 32 halfs, 80B row stride ---------------
__device__ __forceinline__ void ld_tile(uint32_t dst, const hf* __restrict__ g,
                                        int ldg, int rbase, int clampv, int kc,
                                        int rows, int tid) {
    int chunks = rows * 4;
    for (int c = tid; c < chunks; c += 512) {
        int r = c >> 2, cb = (c & 3) << 4;
        int row = rbase + r; if (row > clampv) row = clampv;
        cpa16(dst + (uint32_t)r * 80u + cb,
              (const char*)(g + (size_t)row * ldg + kc) + cb);
    }
}

#define STAGE_B 30720u
#define NSTAGE  4

// ---------------- gate/up GEMM + SwiGLU (CTA 256x64, 16 warps 8x2) -----------
// stage: A 256x32 @ +0 (20480), Bg 64x32 @ +20480 (5120), Bu @ +25600 (5120)
__global__ void __launch_bounds__(512, 1)
gateup_mma(const hf* __restrict__ A, int ldA,
           const hf* __restrict__ BG, const hf* __restrict__ BU,
           size_t bestride, hf* __restrict__ H,
           const int* __restrict__ offs, const int* __restrict__ cnts)
{
    extern __shared__ __align__(256) char smem[];
    int e = blockIdx.z;
    int off = offs[e], cnt = cnts[e];
    int row0 = off + blockIdx.y * 256, rowEnd = off + cnt;
    if (row0 >= rowEnd) return;
    int clampA = rowEnd - 1;
    int n0 = blockIdx.x * 64;
    const hf* bg = BG + (size_t)e * bestride;
    const hf* bu = BU + (size_t)e * bestride;

    uint32_t SB = smem_u32(smem);
    int tid = threadIdx.x, wid = tid >> 5, lane = tid & 31;
    int wm = wid >> 1, wn = wid & 1;

    float accg[2][4][4], accu[2][4][4];
#pragma unroll
    for (int a = 0; a < 2; a++)
#pragma unroll
        for (int b = 0; b < 4; b++)
#pragma unroll
            for (int c = 0; c < 4; c++) { accg[a][b][c] = 0.f; accu[a][b][c] = 0.f; }

    uint32_t aoff = (uint32_t)(wm*32 + (lane & 15)) * 80u + ((lane & 16) ? 16u : 0u);
    uint32_t bpo = (uint32_t)(wn*32 + (lane & 7)) * 80u + ((lane & 8) ? 16u : 0u)
                 + ((lane & 16) ? 640u : 0u);

    const int NCH = CDIM / 32;  // 32
#pragma unroll 1
    for (int i = 0; i < NSTAGE - 1; i++) {
        uint32_t st = SB + (uint32_t)i * STAGE_B;
        int kc = i * 32;
        ld_tile(st +     0, A,  ldA,  row0, clampA,     kc, 256, tid);
        ld_tile(st + 20480, bg, CDIM, n0,   0x7fffffff, kc, 64, tid);
        ld_tile(st + 25600, bu, CDIM, n0,   0x7fffffff, kc, 64, tid);
        CP_COMMIT();
    }
#pragma unroll 1
    for (int i = 0; i < NCH; i++) {
        uint32_t st = SB + (uint32_t)(i & 3) * STAGE_B;
        CP_WAIT2();
        __syncthreads();
        int nc = i + NSTAGE - 1;
        if (nc < NCH) {
            uint32_t wst = SB + (uint32_t)(nc & 3) * STAGE_B;
            int kc = nc * 32;
            ld_tile(wst +     0, A,  ldA,  row0, clampA,     kc, 256, tid);
            ld_tile(wst + 20480, bg, CDIM, n0,   0x7fffffff, kc, 64, tid);
            ld_tile(wst + 25600, bu, CDIM, n0,   0x7fffffff, kc, 64, tid);
        }
        CP_COMMIT();
#pragma unroll
        for (int ks = 0; ks < 2; ks++) {
            uint32_t kb = ks * 32;
            uint32_t af[2][4];
            ldsm4(af[0], st + aoff + kb);
            ldsm4(af[1], st + aoff + 1280 + kb);
            uint32_t bgF[4][2], buF[4][2];
            {
                uint32_t tmp[4];
                ldsm4(tmp, st + 20480 + bpo + kb);
                bgF[0][0]=tmp[0]; bgF[0][1]=tmp[1]; bgF[1][0]=tmp[2]; bgF[1][1]=tmp[3];
                ldsm4(tmp, st + 20480 + bpo + 1280 + kb);
                bgF[2][0]=tmp[0]; bgF[2][1]=tmp[1]; bgF[3][0]=tmp[2]; bgF[3][1]=tmp[3];
                ldsm4(tmp, st + 25600 + bpo + kb);
                buF[0][0]=tmp[0]; buF[0][1]=tmp[1]; buF[1][0]=tmp[2]; buF[1][1]=tmp[3];
                ldsm4(tmp, st + 25600 + bpo + 1280 + kb);
                buF[2][0]=tmp[0]; buF[2][1]=tmp[1]; buF[3][0]=tmp[2]; buF[3][1]=tmp[3];
            }
#pragma unroll
            for (int mt = 0; mt < 2; mt++)
#pragma unroll
                for (int nt = 0; nt < 4; nt++) {
                    mma16816(accg[mt][nt], af[mt], bgF[nt]);
                    mma16816(accu[mt][nt], af[mt], buF[nt]);
                }
        }
    }

    // epilogue: h = silu(g)*u -> fp16
    int gid = lane >> 2, t2 = (lane & 3) * 2;
    int colb = n0 + wn*32 + t2;
#pragma unroll
    for (int mt = 0; mt < 2; mt++) {
        int rbase = row0 + wm*32 + mt*16;
#pragma unroll
        for (int hfx = 0; hfx < 2; hfx++) {
            int r = rbase + gid + hfx*8;
            if (r < rowEnd) {
                size_t ro = (size_t)r * HPAD + colb;
#pragma unroll
                for (int nt = 0; nt < 4; nt++) {
                    float g0 = accg[mt][nt][hfx*2+0], g1 = accg[mt][nt][hfx*2+1];
                    float u0 = accu[mt][nt][hfx*2+0], u1 = accu[mt][nt][hfx*2+1];
                    float h0 = g0 / (1.f + expf(-g0)) * u0;
                    float h1 = g1 / (1.f + expf(-g1)) * u1;
                    *(uint32_t*)(H + ro + nt*8) = packh2(h0, h1);
                }
            }
        }
    }
}

// ---------------- down GEMM (CTA 256x128, 16 warps 4x4) ----------------------
// stage: A 256x32 @ +0 (20480), B 128x32 @ +20480 (10240)
__global__ void __launch_bounds__(512, 1)
down_mma(const hf* __restrict__ A, int ldA,
         const hf* __restrict__ B,
         size_t bestride, float* __restrict__ Y, const float* __restrict__ scale,
         const int* __restrict__ offs, const int* __restrict__ cnts)
{
    extern __shared__ __align__(256) char smem[];
    int e = blockIdx.z;
    int off = offs[e], cnt = cnts[e];
    int row0 = off + blockIdx.y * 256, rowEnd = off + cnt;
    if (row0 >= rowEnd) return;
    int clampA = rowEnd - 1;
    int n0 = blockIdx.x * 128;
    const hf* b_g = B + (size_t)e * bestride;

    uint32_t SB = smem_u32(smem);
    int tid = threadIdx.x, wid = tid >> 5, lane = tid & 31;
    int wm = wid >> 2, wn = wid & 3;

    float acc[4][4][4];
#pragma unroll
    for (int a = 0; a < 4; a++)
#pragma unroll
        for (int b = 0; b < 4; b++)
#pragma unroll
            for (int c = 0; c < 4; c++) acc[a][b][c] = 0.f;

    uint32_t aoff = (uint32_t)(wm*64 + (lane & 15)) * 80u + ((lane & 16) ? 16u : 0u);
    uint32_t bpo = (uint32_t)(wn*32 + (lane & 7)) * 80u + ((lane & 8) ? 16u : 0u)
                 + ((lane & 16) ? 640u : 0u);

    const int NCH = HPAD / 32;  // 88
#pragma unroll 1
    for (int i = 0; i < NSTAGE - 1; i++) {
        uint32_t st = SB + (uint32_t)i * STAGE_B;
        int kc = i * 32;
        ld_tile(st +     0, A,   ldA,  row0, clampA,     kc, 256, tid);
        ld_tile(st + 20480, b_g, HPAD, n0,   0x7fffffff, kc, 128, tid);
        CP_COMMIT();
    }
#pragma unroll 1
    for (int i = 0; i < NCH; i++) {
        uint32_t st = SB + (uint32_t)(i & 3) * STAGE_B;
        CP_WAIT2();
        __syncthreads();
        int nc = i + NSTAGE - 1;
        if (nc < NCH) {
            uint32_t wst = SB + (uint32_t)(nc & 3) * STAGE_B;
            int kc = nc * 32;
            ld_tile(wst +     0, A,   ldA,  row0, clampA,     kc, 256, tid);
            ld_tile(wst + 20480, b_g, HPAD, n0,   0x7fffffff, kc, 128, tid);
        }
        CP_COMMIT();
#pragma unroll
        for (int ks = 0; ks < 2; ks++) {
            uint32_t kb = ks * 32;
            uint32_t af[4][4];
#pragma unroll
            for (int mt = 0; mt < 4; mt++)
                ldsm4(af[mt], st + aoff + mt*1280 + kb);
            uint32_t bF[4][2];
            {
                uint32_t tmp[4];
                ldsm4(tmp, st + 20480 + bpo + kb);
                bF[0][0]=tmp[0]; bF[0][1]=tmp[1]; bF[1][0]=tmp[2]; bF[1][1]=tmp[3];
                ldsm4(tmp, st + 20480 + bpo + 1280 + kb);
                bF[2][0]=tmp[0]; bF[2][1]=tmp[1]; bF[3][0]=tmp[2]; bF[3][1]=tmp[3];
            }
#pragma unroll
            for (int nt = 0; nt < 4; nt++)
#pragma unroll
                for (int mt = 0; mt < 4; mt++)
                    mma16816(acc[mt][nt], af[mt], bF[nt]);
        }
    }

    int gid = lane >> 2, t2 = (lane & 3) * 2;
    int colb = n0 + wn*32 + t2;
#pragma unroll
    for (int mt = 0; mt < 4; mt++) {
        int rbase = row0 + wm*64 + mt*16;
#pragma unroll
        for (int hfx = 0; hfx < 2; hfx++) {
            int r = rbase + gid + hfx*8;
            if (r < rowEnd) {
                float sc = scale ? scale[r] : 1.f;
                float* yp = Y + (size_t)r * CDIM + colb;
#pragma unroll
                for (int nt = 0; nt < 4; nt++) {
                    float2 v;
                    v.x = acc[mt][nt][hfx*2+0] * sc;
                    v.y = acc[mt][nt][hfx*2+1] * sc;
                    *(float2*)(yp + nt*8) = v;
                }
            }
        }
    }
}

// ---------------- combine / aux ----------------------------------------------
__global__ void combine_kernel(float* __restrict__ out) {
    int t = blockIdx.x;
    int p0 = g_pos[t*2+0], p1 = g_pos[t*2+1];
    const float4* a = (const float4*)(g_yd + (size_t)p0 * CDIM);
    const float4* b = (const float4*)(g_yd + (size_t)p1 * CDIM);
    const float4* c = (const float4*)(g_ys + (size_t)t  * CDIM);
    float4* o = (float4*)(out + (size_t)t * CDIM);
    int i = threadIdx.x;
    float4 va = a[i], vb = b[i], vc = c[i];
    o[i] = make_float4(va.x+vb.x+vc.x, va.y+vb.y+vc.y,
                       va.z+vb.z+vc.z, va.w+vb.w+vc.w);
}

__global__ void aux_kernel(float* __restrict__ dst) {
    float a = 0.f;
    for (int e = 0; e < NEXP; e++) {
        float f = (float)g_cnt[e] / (float)(TK * TOPK);
        float p = g_psum[e] / (float)TK;
        a += f * p;
    }
    dst[0] = (float)NEXP * a;
}

// ---------------- launch -----------------------------------------------------
extern "C" void kernel_launch(void* const* d_in, const int* in_sizes, int n_in,
                              void* d_out, int out_size) {
    const float* x  = (const float*)d_in[0];
    const float* rw = (const float*)d_in[1];
    const float* wg = (const float*)d_in[2];
    const float* wu = (const float*)d_in[3];
    const float* wd = (const float*)d_in[4];
    const float* sg = (const float*)d_in[5];
    const float* su = (const float*)d_in[6];
    const float* sd = (const float*)d_in[7];
    float* out = (float*)d_out;

    cudaFuncSetAttribute(gateup_mma, cudaFuncAttributeMaxDynamicSharedMemorySize,
                         NSTAGE * STAGE_B);
    cudaFuncSetAttribute(down_mma, cudaFuncAttributeMaxDynamicSharedMemorySize,
                         NSTAGE * STAGE_B);

    hf *p_xg, *p_xs, *p_wgT, *p_wuT, *p_wdT, *p_sgT, *p_suT, *p_sdT, *p_h, *p_hs;
    float *p_yd, *p_ys, *p_pw;
    int *p_off, *p_cnt, *p_soff, *p_scnt;
    cudaGetSymbolAddress((void**)&p_xg, g_xg);
    cudaGetSymbolAddress((void**)&p_xs, g_xs);
    cudaGetSymbolAddress((void**)&p_wgT, g_wgT);
    cudaGetSymbolAddress((void**)&p_wuT, g_wuT);
    cudaGetSymbolAddress((void**)&p_wdT, g_wdT);
    cudaGetSymbolAddress((void**)&p_sgT, g_sgT);
    cudaGetSymbolAddress((void**)&p_suT, g_suT);
    cudaGetSymbolAddress((void**)&p_sdT, g_sdT);
    cudaGetSymbolAddress((void**)&p_h, g_h);
    cudaGetSymbolAddress((void**)&p_hs, g_hs);
    cudaGetSymbolAddress((void**)&p_yd, g_yd);
    cudaGetSymbolAddress((void**)&p_ys, g_ys);
    cudaGetSymbolAddress((void**)&p_pw, g_pw);
    cudaGetSymbolAddress((void**)&p_off, g_off);
    cudaGetSymbolAddress((void**)&p_cnt, g_cnt);
    cudaGetSymbolAddress((void**)&p_soff, g_soff);
    cudaGetSymbolAddress((void**)&p_scnt, g_scnt);

    zero_kernel<<<1, 32>>>();
    router_kernel<<<TK/4, 128>>>(x, rw);
    offsets_kernel<<<1, 1>>>();
    scatter_kernel<<<16, 256>>>();

    gather_half<<<NPAIR, 256>>>(x);
    xhalf<<<TK, 256>>>(x);

    dim3 tb(32, 8);
    thalf<<<dim3(HPAD/32, CDIM/32, NEXP), tb>>>(wg, CDIM, HDIM,
        (size_t)CDIM*HDIM, p_wgT, CDIM, (size_t)HPAD*CDIM);
    thalf<<<dim3(HPAD/32, CDIM/32, NEXP), tb>>>(wu, CDIM, HDIM,
        (size_t)CDIM*HDIM, p_wuT, CDIM, (size_t)HPAD*CDIM);
    thalf<<<dim3(CDIM/32, HPAD/32, NEXP), tb>>>(wd, HDIM, CDIM,
        (size_t)HDIM*CDIM, p_wdT, HPAD, (size_t)CDIM*HPAD);
    thalf<<<dim3(HPAD/32, CDIM/32, 1), tb>>>(sg, CDIM, HDIM,
        0, p_sgT, CDIM, 0);
    thalf<<<dim3(HPAD/32, CDIM/32, 1), tb>>>(su, CDIM, HDIM,
        0, p_suT, CDIM, 0);
    thalf<<<dim3(CDIM/32, HPAD/32, 1), tb>>>(sd, HDIM, CDIM,
        0, p_sdT, HPAD, 0);

    // expert gate/up + SwiGLU
    gateup_mma<<<dim3(HPAD/64, NPAIR/256, NEXP), 512, NSTAGE*STAGE_B>>>(
        p_xg, CDIM, p_wgT, p_wuT, (size_t)HPAD*CDIM, p_h, p_off, p_cnt);
    // shared gate/up
    gateup_mma<<<dim3(HPAD/64, TK/256, 1), 512, NSTAGE*STAGE_B>>>(
        p_xs, CDIM, p_sgT, p_suT, 0, p_hs, p_soff, p_scnt);

    // expert down (router-weight scaled)
    down_mma<<<dim3(CDIM/128, NPAIR/256, NEXP), 512, NSTAGE*STAGE_B>>>(
        p_h, HPAD, p_wdT, (size_t)CDIM*HPAD, p_yd, p_pw, p_off, p_cnt);
    // shared down
    down_mma<<<dim3(CDIM/128, TK/256, 1), 512, NSTAGE*STAGE_B>>>(
        p_hs, HPAD, p_sdT, 0, p_ys, nullptr, p_soff, p_scnt);

    combine_kernel<<<TK, 256>>>(out);

    if (out_size > TK * CDIM)
        aux_kernel<<<1, 1>>>(out + (size_t)TK * CDIM);
}

// round 10
// speedup vs baseline: 5.2268x; 1.1285x over previous
#include <cuda_runtime.h>
#include <cuda_fp16.h>
#include <math.h>
#include <stdint.h>

#define TK    4096
#define CDIM  1024
#define NEXP  8
#define TOPK  2
#define HDIM  2736
#define HPAD  2816
#define NPAIR (TK*TOPK)

typedef __half hf;

// ---------------- PTX helpers ------------------------------------------------
__device__ __forceinline__ uint32_t smem_u32(const void* p) {
    uint32_t a;
    asm("{ .reg .u64 t; cvta.to.shared.u64 t, %1; cvt.u32.u64 %0, t; }"
        : "=r"(a) : "l"(p));
    return a;
}
__device__ __forceinline__ void cpa16(uint32_t d, const void* s) {
    asm volatile("cp.async.cg.shared.global [%0], [%1], 16;" :: "r"(d), "l"(s));
}
#define CP_COMMIT() asm volatile("cp.async.commit_group;" ::: "memory")
#define CP_WAIT2()  asm volatile("cp.async.wait_group 2;" ::: "memory")

__device__ __forceinline__ void ldsm4(uint32_t* r, uint32_t a) {
    asm volatile("ldmatrix.sync.aligned.m8n8.x4.shared.b16 {%0,%1,%2,%3}, [%4];"
        : "=r"(r[0]), "=r"(r[1]), "=r"(r[2]), "=r"(r[3]) : "r"(a));
}
__device__ __forceinline__ void mma16816(float* d, const uint32_t* a, const uint32_t* b) {
    asm volatile("mma.sync.aligned.m16n8k16.row.col.f32.f16.f16.f32 "
        "{%0,%1,%2,%3}, {%4,%5,%6,%7}, {%8,%9}, {%0,%1,%2,%3};"
        : "+f"(d[0]), "+f"(d[1]), "+f"(d[2]), "+f"(d[3])
        : "r"(a[0]), "r"(a[1]), "r"(a[2]), "r"(a[3]), "r"(b[0]), "r"(b[1]));
}

// ---------------- scratch ----------------------------------------------------
__device__ int   g_cnt[NEXP];
__device__ int   g_off[NEXP];
__device__ int   g_cur[NEXP];
__device__ float g_psum[NEXP];
__device__ int   g_soff[1];
__device__ int   g_scnt[1];
__device__ int   g_top_i[TK*TOPK];
__device__ float g_top_w[TK*TOPK];
__device__ int   g_perm[NPAIR];
__device__ float g_pw[NPAIR];
__device__ int   g_pos[TK*TOPK];

__device__ __align__(256) hf g_xg[(size_t)NPAIR*CDIM];
__device__ __align__(256) hf g_xs[(size_t)TK*CDIM];
__device__ __align__(256) hf g_wgT[(size_t)NEXP*HPAD*CDIM];
__device__ __align__(256) hf g_wuT[(size_t)NEXP*HPAD*CDIM];
__device__ __align__(256) hf g_wdT[(size_t)NEXP*CDIM*HPAD];
__device__ __align__(256) hf g_sgT[(size_t)HPAD*CDIM];
__device__ __align__(256) hf g_suT[(size_t)HPAD*CDIM];
__device__ __align__(256) hf g_sdT[(size_t)CDIM*HPAD];
__device__ __align__(256) hf g_h [(size_t)NPAIR*HPAD];
__device__ __align__(256) hf g_hs[(size_t)TK*HPAD];
__device__ __align__(256) float g_yd[(size_t)NPAIR*CDIM];
__device__ __align__(256) float g_ys[(size_t)TK*CDIM];

// ---------------- small kernels ----------------------------------------------
__global__ void zero_kernel() {
    int t = threadIdx.x;
    if (t < NEXP) { g_cnt[t] = 0; g_psum[t] = 0.f; }
}

__global__ void router_kernel(const float* __restrict__ x,
                              const float* __restrict__ rw) {
    int warp = threadIdx.x >> 5, lane = threadIdx.x & 31;
    int t = blockIdx.x * (blockDim.x >> 5) + warp;
    if (t >= TK) return;
    const float* xr = x + (size_t)t * CDIM;
    float acc[NEXP];
#pragma unroll
    for (int e = 0; e < NEXP; e++) acc[e] = 0.f;
    for (int c = lane; c < CDIM; c += 32) {
        float xv = xr[c];
        const float4* rp = (const float4*)(rw + (size_t)c * NEXP);
        float4 r0 = rp[0], r1 = rp[1];
        acc[0] += xv*r0.x; acc[1] += xv*r0.y; acc[2] += xv*r0.z; acc[3] += xv*r0.w;
        acc[4] += xv*r1.x; acc[5] += xv*r1.y; acc[6] += xv*r1.z; acc[7] += xv*r1.w;
    }
#pragma unroll
    for (int e = 0; e < NEXP; e++)
#pragma unroll
        for (int s = 16; s; s >>= 1)
            acc[e] += __shfl_xor_sync(0xffffffffu, acc[e], s);
    if (lane == 0) {
        int i0 = 0; float v0 = acc[0];
#pragma unroll
        for (int e = 1; e < NEXP; e++) if (acc[e] > v0) { v0 = acc[e]; i0 = e; }
        int i1 = -1; float v1 = -INFINITY;
#pragma unroll
        for (int e = 0; e < NEXP; e++)
            if (e != i0 && acc[e] > v1) { v1 = acc[e]; i1 = e; }
        float w0 = 1.f / (1.f + expf(v1 - v0));
        g_top_i[t*2+0] = i0; g_top_i[t*2+1] = i1;
        g_top_w[t*2+0] = w0; g_top_w[t*2+1] = 1.f - w0;
        atomicAdd(&g_cnt[i0], 1); atomicAdd(&g_cnt[i1], 1);
        float s = 0.f, pe[NEXP];
#pragma unroll
        for (int e = 0; e < NEXP; e++) { pe[e] = expf(acc[e] - v0); s += pe[e]; }
        float inv = 1.f / s;
#pragma unroll
        for (int e = 0; e < NEXP; e++) atomicAdd(&g_psum[e], pe[e] * inv);
    }
}

__global__ void offsets_kernel() {
    int o = 0;
    for (int e = 0; e < NEXP; e++) { g_off[e] = o; g_cur[e] = o; o += g_cnt[e]; }
    g_soff[0] = 0; g_scnt[0] = TK;
}

__global__ void scatter_kernel() {
    int t = blockIdx.x * blockDim.x + threadIdx.x;
    if (t >= TK) return;
#pragma unroll
    for (int k = 0; k < TOPK; k++) {
        int e = g_top_i[t*2+k];
        int pos = atomicAdd(&g_cur[e], 1);
        g_perm[pos] = t;
        g_pw[pos]   = g_top_w[t*2+k];
        g_pos[t*2+k] = pos;
    }
}

__device__ __forceinline__ uint32_t packh2(float a, float b) {
    __half2 t = __floats2half2_rn(a, b);
    return *reinterpret_cast<uint32_t*>(&t);
}

__global__ void gather_half(const float* __restrict__ x) {
    int p = blockIdx.x;
    int src = g_perm[p];
    float4 v = ((const float4*)(x + (size_t)src * CDIM))[threadIdx.x];
    uint2 h;
    h.x = packh2(v.x, v.y); h.y = packh2(v.z, v.w);
    ((uint2*)(g_xg + (size_t)p * CDIM))[threadIdx.x] = h;
}

__global__ void xhalf(const float* __restrict__ x) {
    int t = blockIdx.x;
    float4 v = ((const float4*)(x + (size_t)t * CDIM))[threadIdx.x];
    uint2 h;
    h.x = packh2(v.x, v.y); h.y = packh2(v.z, v.w);
    ((uint2*)(g_xs + (size_t)t * CDIM))[threadIdx.x] = h;
}

// transpose+convert: in [K,N] fp32 -> out [Npad rows][Kpad cols] fp16
__global__ void thalf(const float* __restrict__ in, int K, int N, size_t in_bs,
                      hf* __restrict__ oh, int Kpad, size_t out_bs) {
    __shared__ float t[32][33];
    int b = blockIdx.z;
    in += (size_t)b * in_bs; oh += (size_t)b * out_bs;
    int nb = blockIdx.x * 32, kb = blockIdx.y * 32;
    int tx = threadIdx.x, ty = threadIdx.y;
#pragma unroll
    for (int i = 0; i < 4; i++) {
        int k = kb + ty + i*8, n = nb + tx;
        t[ty + i*8][tx] = (k < K && n < N) ? in[(size_t)k * N + n] : 0.f;
    }
    __syncthreads();
#pragma unroll
    for (int i = 0; i < 4; i++) {
        int n = nb + ty + i*8, k = kb + tx;
        oh[(size_t)n * Kpad + k] = __float2half_rn(t[tx][ty + i*8]);
    }
}

// ---------------- tile loader: rows x 32 halfs, 80B row stride ---------------
__device__ __forceinline__ void ld_tile(uint32_t dst, const hf* __restrict__ g,
                                        int ldg, int rbase, int clampv, int kc,
                                        int rows, int tid) {
    int chunks = rows * 4;
    for (int c = tid; c < chunks; c += 512) {
        int r = c >> 2, cb = (c & 3) << 4;
        int row = rbase + r; if (row > clampv) row = clampv;
        cpa16(dst + (uint32_t)r * 80u + cb,
              (const char*)(g + (size_t)row * ldg + kc) + cb);
    }
}

#define STAGE_B 30720u
#define NSTAGE  4

// ---------------- gate/up GEMM + SwiGLU (CTA 256x64, 16 warps 8x2) -----------
__global__ void __launch_bounds__(512, 1)
gateup_mma(const hf* __restrict__ A, int ldA,
           const hf* __restrict__ BG, const hf* __restrict__ BU,
           size_t bestride, hf* __restrict__ H,
           const int* __restrict__ offs, const int* __restrict__ cnts)
{
    extern __shared__ __align__(256) char smem[];
    int e = blockIdx.z;
    int off = offs[e], cnt = cnts[e];
    int row0 = off + blockIdx.y * 256, rowEnd = off + cnt;
    if (row0 >= rowEnd) return;
    int clampA = rowEnd - 1;
    int n0 = blockIdx.x * 64;
    const hf* bg = BG + (size_t)e * bestride;
    const hf* bu = BU + (size_t)e * bestride;

    uint32_t SB = smem_u32(smem);
    int tid = threadIdx.x, wid = tid >> 5, lane = tid & 31;
    int wm = wid >> 1, wn = wid & 1;

    float accg[2][4][4], accu[2][4][4];
#pragma unroll
    for (int a = 0; a < 2; a++)
#pragma unroll
        for (int b = 0; b < 4; b++)
#pragma unroll
            for (int c = 0; c < 4; c++) { accg[a][b][c] = 0.f; accu[a][b][c] = 0.f; }

    uint32_t aoff = (uint32_t)(wm*32 + (lane & 15)) * 80u + ((lane & 16) ? 16u : 0u);
    uint32_t bpo = (uint32_t)(wn*32 + (lane & 7)) * 80u + ((lane & 8) ? 16u : 0u)
                 + ((lane & 16) ? 640u : 0u);

    const int NCH = CDIM / 32;  // 32
#pragma unroll 1
    for (int i = 0; i < NSTAGE - 1; i++) {
        uint32_t st = SB + (uint32_t)i * STAGE_B;
        int kc = i * 32;
        ld_tile(st +     0, A,  ldA,  row0, clampA,     kc, 256, tid);
        ld_tile(st + 20480, bg, CDIM, n0,   0x7fffffff, kc, 64, tid);
        ld_tile(st + 25600, bu, CDIM, n0,   0x7fffffff, kc, 64, tid);
        CP_COMMIT();
    }
#pragma unroll 1
    for (int i = 0; i < NCH; i++) {
        uint32_t st = SB + (uint32_t)(i & 3) * STAGE_B;
        CP_WAIT2();
        __syncthreads();
        int nc = i + NSTAGE - 1;
        if (nc < NCH) {
            uint32_t wst = SB + (uint32_t)(nc & 3) * STAGE_B;
            int kc = nc * 32;
            ld_tile(wst +     0, A,  ldA,  row0, clampA,     kc, 256, tid);
            ld_tile(wst + 20480, bg, CDIM, n0,   0x7fffffff, kc, 64, tid);
            ld_tile(wst + 25600, bu, CDIM, n0,   0x7fffffff, kc, 64, tid);
        }
        CP_COMMIT();
#pragma unroll
        for (int ks = 0; ks < 2; ks++) {
            uint32_t kb = ks * 32;
            uint32_t af[2][4];
            ldsm4(af[0], st + aoff + kb);
            ldsm4(af[1], st + aoff + 1280 + kb);
            uint32_t bgF[4][2], buF[4][2];
            {
                uint32_t tmp[4];
                ldsm4(tmp, st + 20480 + bpo + kb);
                bgF[0][0]=tmp[0]; bgF[0][1]=tmp[1]; bgF[1][0]=tmp[2]; bgF[1][1]=tmp[3];
                ldsm4(tmp, st + 20480 + bpo + 1280 + kb);
                bgF[2][0]=tmp[0]; bgF[2][1]=tmp[1]; bgF[3][0]=tmp[2]; bgF[3][1]=tmp[3];
                ldsm4(tmp, st + 25600 + bpo + kb);
                buF[0][0]=tmp[0]; buF[0][1]=tmp[1]; buF[1][0]=tmp[2]; buF[1][1]=tmp[3];
                ldsm4(tmp, st + 25600 + bpo + 1280 + kb);
                buF[2][0]=tmp[0]; buF[2][1]=tmp[1]; buF[3][0]=tmp[2]; buF[3][1]=tmp[3];
            }
#pragma unroll
            for (int mt = 0; mt < 2; mt++)
#pragma unroll
                for (int nt = 0; nt < 4; nt++) {
                    mma16816(accg[mt][nt], af[mt], bgF[nt]);
                    mma16816(accu[mt][nt], af[mt], buF[nt]);
                }
        }
    }

    // epilogue: h = silu(g)*u -> fp16
    int gid = lane >> 2, t2 = (lane & 3) * 2;
    int colb = n0 + wn*32 + t2;
#pragma unroll
    for (int mt = 0; mt < 2; mt++) {
        int rbase = row0 + wm*32 + mt*16;
#pragma unroll
        for (int hfx = 0; hfx < 2; hfx++) {
            int r = rbase + gid + hfx*8;
            if (r < rowEnd) {
                size_t ro = (size_t)r * HPAD + colb;
#pragma unroll
                for (int nt = 0; nt < 4; nt++) {
                    float g0 = accg[mt][nt][hfx*2+0], g1 = accg[mt][nt][hfx*2+1];
                    float u0 = accu[mt][nt][hfx*2+0], u1 = accu[mt][nt][hfx*2+1];
                    float h0 = g0 / (1.f + expf(-g0)) * u0;
                    float h1 = g1 / (1.f + expf(-g1)) * u1;
                    *(uint32_t*)(H + ro + nt*8) = packh2(h0, h1);
                }
            }
        }
    }
}

// ---------------- down GEMM (CTA 256x128, 16 warps 4x4) ----------------------
__global__ void __launch_bounds__(512, 1)
down_mma(const hf* __restrict__ A, int ldA,
         const hf* __restrict__ B,
         size_t bestride, float* __restrict__ Y, const float* __restrict__ scale,
         const int* __restrict__ offs, const int* __restrict__ cnts)
{
    extern __shared__ __align__(256) char smem[];
    int e = blockIdx.z;
    int off = offs[e], cnt = cnts[e];
    int row0 = off + blockIdx.y * 256, rowEnd = off + cnt;
    if (row0 >= rowEnd) return;
    int clampA = rowEnd - 1;
    int n0 = blockIdx.x * 128;
    const hf* b_g = B + (size_t)e * bestride;

    uint32_t SB = smem_u32(smem);
    int tid = threadIdx.x, wid = tid >> 5, lane = tid & 31;
    int wm = wid >> 2, wn = wid & 3;

    float acc[4][4][4];
#pragma unroll
    for (int a = 0; a < 4; a++)
#pragma unroll
        for (int b = 0; b < 4; b++)
#pragma unroll
            for (int c = 0; c < 4; c++) acc[a][b][c] = 0.f;

    uint32_t aoff = (uint32_t)(wm*64 + (lane & 15)) * 80u + ((lane & 16) ? 16u : 0u);
    uint32_t bpo = (uint32_t)(wn*32 + (lane & 7)) * 80u + ((lane & 8) ? 16u : 0u)
                 + ((lane & 16) ? 640u : 0u);

    const int NCH = HPAD / 32;  // 88
#pragma unroll 1
    for (int i = 0; i < NSTAGE - 1; i++) {
        uint32_t st = SB + (uint32_t)i * STAGE_B;
        int kc = i * 32;
        ld_tile(st +     0, A,   ldA,  row0, clampA,     kc, 256, tid);
        ld_tile(st + 20480, b_g, HPAD, n0,   0x7fffffff, kc, 128, tid);
        CP_COMMIT();
    }
#pragma unroll 1
    for (int i = 0; i < NCH; i++) {
        uint32_t st = SB + (uint32_t)(i & 3) * STAGE_B;
        CP_WAIT2();
        __syncthreads();
        int nc = i + NSTAGE - 1;
        if (nc < NCH) {
            uint32_t wst = SB + (uint32_t)(nc & 3) * STAGE_B;
            int kc = nc * 32;
            ld_tile(wst +     0, A,   ldA,  row0, clampA,     kc, 256, tid);
            ld_tile(wst + 20480, b_g, HPAD, n0,   0x7fffffff, kc, 128, tid);
        }
        CP_COMMIT();
#pragma unroll
        for (int ks = 0; ks < 2; ks++) {
            uint32_t kb = ks * 32;
            uint32_t af[4][4];
#pragma unroll
            for (int mt = 0; mt < 4; mt++)
                ldsm4(af[mt], st + aoff + mt*1280 + kb);
            uint32_t bF[4][2];
            {
                uint32_t tmp[4];
                ldsm4(tmp, st + 20480 + bpo + kb);
                bF[0][0]=tmp[0]; bF[0][1]=tmp[1]; bF[1][0]=tmp[2]; bF[1][1]=tmp[3];
                ldsm4(tmp, st + 20480 + bpo + 1280 + kb);
                bF[2][0]=tmp[0]; bF[2][1]=tmp[1]; bF[3][0]=tmp[2]; bF[3][1]=tmp[3];
            }
#pragma unroll
            for (int nt = 0; nt < 4; nt++)
#pragma unroll
                for (int mt = 0; mt < 4; mt++)
                    mma16816(acc[mt][nt], af[mt], bF[nt]);
        }
    }

    int gid = lane >> 2, t2 = (lane & 3) * 2;
    int colb = n0 + wn*32 + t2;
#pragma unroll
    for (int mt = 0; mt < 4; mt++) {
        int rbase = row0 + wm*64 + mt*16;
#pragma unroll
        for (int hfx = 0; hfx < 2; hfx++) {
            int r = rbase + gid + hfx*8;
            if (r < rowEnd) {
                float sc = scale ? scale[r] : 1.f;
                float* yp = Y + (size_t)r * CDIM + colb;
#pragma unroll
                for (int nt = 0; nt < 4; nt++) {
                    float2 v;
                    v.x = acc[mt][nt][hfx*2+0] * sc;
                    v.y = acc[mt][nt][hfx*2+1] * sc;
                    *(float2*)(yp + nt*8) = v;
                }
            }
        }
    }
}

// ---------------- combine / aux ----------------------------------------------
__global__ void combine_kernel(float* __restrict__ out) {
    int t = blockIdx.x;
    int p0 = g_pos[t*2+0], p1 = g_pos[t*2+1];
    const float4* a = (const float4*)(g_yd + (size_t)p0 * CDIM);
    const float4* b = (const float4*)(g_yd + (size_t)p1 * CDIM);
    const float4* c = (const float4*)(g_ys + (size_t)t  * CDIM);
    float4* o = (float4*)(out + (size_t)t * CDIM);
    int i = threadIdx.x;
    float4 va = a[i], vb = b[i], vc = c[i];
    o[i] = make_float4(va.x+vb.x+vc.x, va.y+vb.y+vc.y,
                       va.z+vb.z+vc.z, va.w+vb.w+vc.w);
}

__global__ void aux_kernel(float* __restrict__ dst) {
    float a = 0.f;
    for (int e = 0; e < NEXP; e++) {
        float f = (float)g_cnt[e] / (float)(TK * TOPK);
        float p = g_psum[e] / (float)TK;
        a += f * p;
    }
    dst[0] = (float)NEXP * a;
}

// ---------------- launch -----------------------------------------------------
extern "C" void kernel_launch(void* const* d_in, const int* in_sizes, int n_in,
                              void* d_out, int out_size) {
    const float* x  = (const float*)d_in[0];
    const float* rw = (const float*)d_in[1];
    const float* wg = (const float*)d_in[2];
    const float* wu = (const float*)d_in[3];
    const float* wd = (const float*)d_in[4];
    const float* sg = (const float*)d_in[5];
    const float* su = (const float*)d_in[6];
    const float* sd = (const float*)d_in[7];
    float* out = (float*)d_out;

    cudaFuncSetAttribute(gateup_mma, cudaFuncAttributeMaxDynamicSharedMemorySize,
                         NSTAGE * STAGE_B);
    cudaFuncSetAttribute(down_mma, cudaFuncAttributeMaxDynamicSharedMemorySize,
                         NSTAGE * STAGE_B);

    // streams / events for fork-join overlap (created once; host-side only)
    static cudaStream_t s1 = nullptr, s2 = nullptr, s3 = nullptr;
    static cudaEvent_t evF, evGU, evWD, evSD, evDS;
    if (!s1) {
        cudaStreamCreateWithFlags(&s1, cudaStreamNonBlocking);
        cudaStreamCreateWithFlags(&s2, cudaStreamNonBlocking);
        cudaStreamCreateWithFlags(&s3, cudaStreamNonBlocking);
        cudaEventCreateWithFlags(&evF,  cudaEventDisableTiming);
        cudaEventCreateWithFlags(&evGU, cudaEventDisableTiming);
        cudaEventCreateWithFlags(&evWD, cudaEventDisableTiming);
        cudaEventCreateWithFlags(&evSD, cudaEventDisableTiming);
        cudaEventCreateWithFlags(&evDS, cudaEventDisableTiming);
    }

    hf *p_xg, *p_xs, *p_wgT, *p_wuT, *p_wdT, *p_sgT, *p_suT, *p_sdT, *p_h, *p_hs;
    float *p_yd, *p_ys, *p_pw;
    int *p_off, *p_cnt, *p_soff, *p_scnt;
    cudaGetSymbolAddress((void**)&p_xg, g_xg);
    cudaGetSymbolAddress((void**)&p_xs, g_xs);
    cudaGetSymbolAddress((void**)&p_wgT, g_wgT);
    cudaGetSymbolAddress((void**)&p_wuT, g_wuT);
    cudaGetSymbolAddress((void**)&p_wdT, g_wdT);
    cudaGetSymbolAddress((void**)&p_sgT, g_sgT);
    cudaGetSymbolAddress((void**)&p_suT, g_suT);
    cudaGetSymbolAddress((void**)&p_sdT, g_sdT);
    cudaGetSymbolAddress((void**)&p_h, g_h);
    cudaGetSymbolAddress((void**)&p_hs, g_hs);
    cudaGetSymbolAddress((void**)&p_yd, g_yd);
    cudaGetSymbolAddress((void**)&p_ys, g_ys);
    cudaGetSymbolAddress((void**)&p_pw, g_pw);
    cudaGetSymbolAddress((void**)&p_off, g_off);
    cudaGetSymbolAddress((void**)&p_cnt, g_cnt);
    cudaGetSymbolAddress((void**)&p_soff, g_soff);
    cudaGetSymbolAddress((void**)&p_scnt, g_scnt);

    dim3 tb(32, 8);

    // fork point on legacy stream
    zero_kernel<<<1, 32>>>();
    cudaEventRecord(evF, 0);
    cudaStreamWaitEvent(s1, evF, 0);
    cudaStreamWaitEvent(s2, evF, 0);
    cudaStreamWaitEvent(s3, evF, 0);

    // s1: expert gate/up weight conversion
    thalf<<<dim3(HPAD/32, CDIM/32, NEXP), tb, 0, s1>>>(wg, CDIM, HDIM,
        (size_t)CDIM*HDIM, p_wgT, CDIM, (size_t)HPAD*CDIM);
    thalf<<<dim3(HPAD/32, CDIM/32, NEXP), tb, 0, s1>>>(wu, CDIM, HDIM,
        (size_t)CDIM*HDIM, p_wuT, CDIM, (size_t)HPAD*CDIM);
    cudaEventRecord(evGU, s1);

    // s2: down weight conversions
    thalf<<<dim3(CDIM/32, HPAD/32, NEXP), tb, 0, s2>>>(wd, HDIM, CDIM,
        (size_t)HDIM*CDIM, p_wdT, HPAD, (size_t)CDIM*HPAD);
    cudaEventRecord(evWD, s2);
    thalf<<<dim3(CDIM/32, HPAD/32, 1), tb, 0, s2>>>(sd, HDIM, CDIM,
        0, p_sdT, HPAD, 0);
    cudaEventRecord(evSD, s2);

    // s3: shared-expert branch (x convert, sg/su convert, gateup, down)
    xhalf<<<TK, 256, 0, s3>>>(x);
    thalf<<<dim3(HPAD/32, CDIM/32, 1), tb, 0, s3>>>(sg, CDIM, HDIM,
        0, p_sgT, CDIM, 0);
    thalf<<<dim3(HPAD/32, CDIM/32, 1), tb, 0, s3>>>(su, CDIM, HDIM,
        0, p_suT, CDIM, 0);
    gateup_mma<<<dim3(HPAD/64, TK/256, 1), 512, NSTAGE*STAGE_B, s3>>>(
        p_xs, CDIM, p_sgT, p_suT, 0, p_hs, p_soff, p_scnt);
    cudaStreamWaitEvent(s3, evSD, 0);
    down_mma<<<dim3(CDIM/128, TK/256, 1), 512, NSTAGE*STAGE_B, s3>>>(
        p_hs, HPAD, p_sdT, 0, p_ys, nullptr, p_soff, p_scnt);
    cudaEventRecord(evDS, s3);

    // main: router chain + expert branch
    router_kernel<<<TK/4, 128>>>(x, rw);
    offsets_kernel<<<1, 1>>>();
    scatter_kernel<<<16, 256>>>();
    gather_half<<<NPAIR, 256>>>(x);

    cudaStreamWaitEvent(0, evGU, 0);
    gateup_mma<<<dim3(HPAD/64, NPAIR/256, NEXP), 512, NSTAGE*STAGE_B>>>(
        p_xg, CDIM, p_wgT, p_wuT, (size_t)HPAD*CDIM, p_h, p_off, p_cnt);

    cudaStreamWaitEvent(0, evWD, 0);
    down_mma<<<dim3(CDIM/128, NPAIR/256, NEXP), 512, NSTAGE*STAGE_B>>>(
        p_h, HPAD, p_wdT, (size_t)CDIM*HPAD, p_yd, p_pw, p_off, p_cnt);

    cudaStreamWaitEvent(0, evDS, 0);
    combine_kernel<<<TK, 256>>>(out);

    if (out_size > TK * CDIM)
        aux_kernel<<<1, 1>>>(out + (size_t)TK * CDIM);
}